// round 9
// baseline (speedup 1.0000x reference)
#include <cuda_runtime.h>
#include <cuda_bf16.h>
#include <math.h>
#include <stdint.h>

// Problem dims
#define NB 8
#define CC 512
#define SS 4096     // N = H*W tokens
#define HD 2048     // HID = 4*C
#define HH 64

#define KCHUNK 16   // column-softmax chunks

// ---------------- scratch (device globals; no allocation allowed) ----------
__device__ float g_q  [(long long)NB*CC*SS];
__device__ float g_k  [(long long)NB*CC*SS];
__device__ float g_kt [(long long)NB*CC*SS];
__device__ float g_v  [(long long)NB*CC*SS];
__device__ float g_sc [(long long)NB*SS*CC];
__device__ float g_enh[(long long)NB*SS*CC];
__device__ float g_t  [(long long)NB*SS*CC];
__device__ float g_a  [(long long)NB*SS*HD];
__device__ float g_ax [(long long)NB*SS*HD];
__device__ float g_kv [(long long)NB*CC*CC];
__device__ float g_kvp[(long long)4*NB*CC*CC];   // split-K partials
__device__ float g_wqh[CC*CC], g_wql[CC*CC];
__device__ float g_wkh[CC*CC], g_wkl[CC*CC];
__device__ float g_wv [CC*CC];
__device__ float g_w1 [(long long)CC*HD];
__device__ float g_w2 [(long long)HD*CC];
__device__ float g_ksum[NB*CC];
__device__ float g_z  [NB*SS];
__device__ float g_cpm[NB*CC*KCHUNK];
__device__ float g_cps[NB*CC*KCHUNK];
__device__ float g_cfm[NB*CC];
__device__ float g_cfi[NB*CC];

// ---------------- helpers ---------------------------------------------------
__device__ __forceinline__ float blockReduceSum(float val) {
    __shared__ float sh[32];
    int lane = threadIdx.x & 31, wid = threadIdx.x >> 5;
    #pragma unroll
    for (int o = 16; o > 0; o >>= 1) val += __shfl_xor_sync(0xffffffff, val, o);
    if (lane == 0) sh[wid] = val;
    __syncthreads();
    float tot = 0.f;
    if (wid == 0) {
        tot = (lane < (int)(blockDim.x >> 5)) ? sh[lane] : 0.f;
        #pragma unroll
        for (int o = 16; o > 0; o >>= 1) tot += __shfl_xor_sync(0xffffffff, tot, o);
        if (lane == 0) sh[0] = tot;
    }
    __syncthreads();
    tot = sh[0];
    __syncthreads();
    return tot;
}

__device__ __forceinline__ float blockReduceMax(float val) {
    __shared__ float sh[32];
    int lane = threadIdx.x & 31, wid = threadIdx.x >> 5;
    #pragma unroll
    for (int o = 16; o > 0; o >>= 1) val = fmaxf(val, __shfl_xor_sync(0xffffffff, val, o));
    if (lane == 0) sh[wid] = val;
    __syncthreads();
    float tot = -1e30f;
    if (wid == 0) {
        tot = (lane < (int)(blockDim.x >> 5)) ? sh[lane] : -1e30f;
        #pragma unroll
        for (int o = 16; o > 0; o >>= 1) tot = fmaxf(tot, __shfl_xor_sync(0xffffffff, tot, o));
        if (lane == 0) sh[0] = tot;
    }
    __syncthreads();
    tot = sh[0];
    __syncthreads();
    return tot;
}

__device__ __forceinline__ float cvt_tf32(float v) {
    uint32_t u;
    asm("cvt.rna.tf32.f32 %0, %1;" : "=r"(u) : "f"(v));
    return __uint_as_float(u);
}

__device__ __forceinline__ void cp16(uint32_t s, const void* g) {
    asm volatile("cp.async.cg.shared.global [%0], [%1], 16;" :: "r"(s), "l"(g));
}

#define MMA_TF32(d, a, b) \
    asm volatile("mma.sync.aligned.m16n8k8.row.col.f32.tf32.tf32.f32 " \
        "{%0,%1,%2,%3},{%4,%5,%6,%7},{%8,%9},{%0,%1,%2,%3};" \
        : "+f"(d[0]), "+f"(d[1]), "+f"(d[2]), "+f"(d[3]) \
        : "r"(a[0]), "r"(a[1]), "r"(a[2]), "r"(a[3]), "r"(b[0]), "r"(b[1]))

#define LDMX4(dst, addr) \
    asm volatile("ldmatrix.sync.aligned.m8n8.x4.shared.b16 {%0,%1,%2,%3}, [%4];" \
        : "=r"(dst[0]), "=r"(dst[1]), "=r"(dst[2]), "=r"(dst[3]) : "r"(addr) : "memory")

// smem layouts: BK=32.  A rows padded to 36 floats (144B), B rows 136 floats.
#define TCSTAGES 3
#define AS_FLOATS (TCSTAGES * 128 * 36)
#define BS_FLOATS (TCSTAGES * 32 * 136)
#define SMEM_GEMM_BYTES ((AS_FLOATS + BS_FLOATS) * 4)
// split2: 2 stages, A hi+lo planes + B
#define SMEM_SPLIT2_BYTES ((2*2*128*36 + 2*32*136) * 4)

// ---------------- single-pass TF32 GEMM, BK=32, 3-stage cp.async -----------
// A must be pre-rounded tf32. B pre-rounded unless CVTB.
// MODE: 0 = +bias[row]; 1 = plain; 2 = acc*z[row]+shortcut; 3 = +bias[col];
//       4 = +bias[col]+res.  RND: tf32-round stores.  SPLITK: 4-way K split
//       (blockIdx.z = batch*4+slice, K param = lda, keff = 1024).
template<int MODE, bool CVTB, bool RND, bool SPLITK>
__global__ void __launch_bounds__(256, 2)
gemm_tc(const float* __restrict__ A, const float* __restrict__ B,
        float* __restrict__ C, int M, int N, int K,
        long long strA, long long strB, long long strC,
        const float* __restrict__ e0, const float* __restrict__ e1,
        long long strE0, long long strE1)
{
    extern __shared__ float smem[];
    float* Asm = smem;
    float* Bsm = smem + AS_FLOATS;

    int bz = blockIdx.z;
    int keff = K;
    if (SPLITK) {
        int slice = bz & 3;
        int batch = bz >> 2;
        A += (long long)batch * strA + slice * 1024;
        B += (long long)batch * strB + (long long)slice * 1024 * N;
        C += (long long)bz * strC;
        keff = 1024;
    } else {
        A += (long long)bz * strA;
        B += (long long)bz * strB;
        C += (long long)bz * strC;
    }
    const float* E0 = e0 ? e0 + (long long)bz * strE0 : nullptr;
    const float* E1 = e1 ? e1 + (long long)bz * strE1 : nullptr;

    const int t    = threadIdx.x;
    const int lane = t & 31, warp = t >> 5;
    const int m0   = blockIdx.y * 128, n0 = blockIdx.x * 128;
    const int wm0  = (warp & 1) * 64;
    const int wn0  = (warp >> 1) * 32;

    // copy assignment: A 128x32 (2 thr/row x 16 floats), B 32x128 (8 thr/row)
    const int arow = t >> 1,  acol = (t & 1) * 16;
    const int brow = t >> 3,  bcol = (t & 7) * 16;

    const uint32_t sA = (uint32_t)__cvta_generic_to_shared(Asm);
    const uint32_t sB = (uint32_t)__cvta_generic_to_shared(Bsm);

    float acc[4][4][4];
    #pragma unroll
    for (int i = 0; i < 4; i++)
        #pragma unroll
        for (int j = 0; j < 4; j++)
            #pragma unroll
            for (int r = 0; r < 4; r++) acc[i][j][r] = 0.f;

    const int aRow    = wm0 + (lane & 15);
    const int aColSel = (lane >> 4) << 2;
    const int bkRow   = lane & 3;
    const int bnCol   = wn0 + (lane >> 2);

    const int nk = keff >> 5;   // BK = 32

    auto load_stage = [&](int kt, int buf) {
        const float* ap = A + (long long)(m0 + arow) * K + (kt << 5) + acol;
        uint32_t sa = sA + (uint32_t)(((buf * 128 + arow) * 36 + acol) << 2);
        cp16(sa,      ap);
        cp16(sa + 16, ap + 4);
        cp16(sa + 32, ap + 8);
        cp16(sa + 48, ap + 12);
        const float* bp = B + (long long)((kt << 5) + brow) * N + n0 + bcol;
        uint32_t sb = sB + (uint32_t)(((buf * 32 + brow) * 136 + bcol) << 2);
        cp16(sb,      bp);
        cp16(sb + 16, bp + 4);
        cp16(sb + 32, bp + 8);
        cp16(sb + 48, bp + 12);
    };

    #pragma unroll
    for (int s = 0; s < 2; s++) {
        if (s < nk) load_stage(s, s);
        asm volatile("cp.async.commit_group;" ::: "memory");
    }

    for (int kt = 0; kt < nk; kt++) {
        asm volatile("cp.async.wait_group 1;" ::: "memory");
        __syncthreads();
        {
            int pf = kt + 2;
            if (pf < nk) load_stage(pf, pf % 3);
            asm volatile("cp.async.commit_group;" ::: "memory");
        }
        const int buf = kt % 3;

        #pragma unroll
        for (int k8 = 0; k8 < 32; k8 += 8) {
            uint32_t ah[4][4];
            #pragma unroll
            for (int mt = 0; mt < 4; mt++) {
                uint32_t addr = sA +
                    ((uint32_t)(((buf * 128 + aRow + mt * 16) * 36) + k8 + aColSel) << 2);
                LDMX4(ah[mt], addr);
            }
            uint32_t bh[4][2];
            #pragma unroll
            for (int nt = 0; nt < 4; nt++) {
                #pragma unroll
                for (int j = 0; j < 2; j++) {
                    float f = Bsm[(buf * 32 + k8 + bkRow + j * 4) * 136 + bnCol + nt * 8];
                    bh[nt][j] = __float_as_uint(CVTB ? cvt_tf32(f) : f);
                }
            }
            #pragma unroll
            for (int mt = 0; mt < 4; mt++)
                #pragma unroll
                for (int nt = 0; nt < 4; nt++)
                    MMA_TF32(acc[mt][nt], ah[mt], bh[nt]);
        }
    }

    #pragma unroll
    for (int mt = 0; mt < 4; mt++) {
        #pragma unroll
        for (int half = 0; half < 2; half++) {
            int r = m0 + wm0 + mt * 16 + (lane >> 2) + half * 8;
            #pragma unroll
            for (int nt = 0; nt < 4; nt++) {
                int c = n0 + wn0 + nt * 8 + (lane & 3) * 2;
                float v0 = acc[mt][nt][half * 2 + 0];
                float v1 = acc[mt][nt][half * 2 + 1];
                long long off = (long long)r * N + c;
                if (MODE == 0) { float b = E0[r]; v0 += b; v1 += b; }
                if (MODE == 2) {
                    float zz = E0[r];
                    float2 s = *reinterpret_cast<const float2*>(&E1[off]);
                    v0 = v0 * zz + s.x; v1 = v1 * zz + s.y;
                }
                if (MODE == 3) { v0 += E0[c]; v1 += E0[c + 1]; }
                if (MODE == 4) {
                    float2 s = *reinterpret_cast<const float2*>(&E1[off]);
                    v0 += E0[c] + s.x; v1 += E0[c + 1] + s.y;
                }
                if (RND) { v0 = cvt_tf32(v0); v1 = cvt_tf32(v1); }
                *reinterpret_cast<float2*>(&C[off]) = make_float2(v0, v1);
            }
        }
    }
}

// ---------------- split (3xTF32) GEMM: A pre-split planes, B reg-split ------
// C = Ah@Bh + Ah@Bl + Al@Bh + bias[row].  BK=32, 2-stage cp.async.
__global__ void __launch_bounds__(256, 2)
gemm_split2(const float* __restrict__ Ah, const float* __restrict__ Al,
            const float* __restrict__ B, float* __restrict__ C,
            int M, int N, int K, long long strB, long long strC,
            const float* __restrict__ bias)
{
    extern __shared__ float smem[];
    float* AsH = smem;                          // [2][128][36]
    float* AsL = AsH + 2 * 128 * 36;
    float* Bsm = AsL + 2 * 128 * 36;            // [2][32][136]

    const int bz = blockIdx.z;
    B += (long long)bz * strB;
    C += (long long)bz * strC;

    const int t    = threadIdx.x;
    const int lane = t & 31, warp = t >> 5;
    const int m0   = blockIdx.y * 128, n0 = blockIdx.x * 128;
    const int wm0  = (warp & 1) * 64;
    const int wn0  = (warp >> 1) * 32;

    const int arow = t >> 1,  acol = (t & 1) * 16;
    const int brow = t >> 3,  bcol = (t & 7) * 16;

    const uint32_t sAH = (uint32_t)__cvta_generic_to_shared(AsH);
    const uint32_t sAL = (uint32_t)__cvta_generic_to_shared(AsL);
    const uint32_t sB  = (uint32_t)__cvta_generic_to_shared(Bsm);

    float acc[4][4][4];
    #pragma unroll
    for (int i = 0; i < 4; i++)
        #pragma unroll
        for (int j = 0; j < 4; j++)
            #pragma unroll
            for (int r = 0; r < 4; r++) acc[i][j][r] = 0.f;

    const int aRow    = wm0 + (lane & 15);
    const int aColSel = (lane >> 4) << 2;
    const int bkRow   = lane & 3;
    const int bnCol   = wn0 + (lane >> 2);

    const int nk = K >> 5;

    auto load_stage = [&](int kt, int buf) {
        long long aoff = (long long)(m0 + arow) * K + (kt << 5) + acol;
        uint32_t soA = (uint32_t)(((buf * 128 + arow) * 36 + acol) << 2);
        cp16(sAH + soA,      Ah + aoff);
        cp16(sAH + soA + 16, Ah + aoff + 4);
        cp16(sAH + soA + 32, Ah + aoff + 8);
        cp16(sAH + soA + 48, Ah + aoff + 12);
        cp16(sAL + soA,      Al + aoff);
        cp16(sAL + soA + 16, Al + aoff + 4);
        cp16(sAL + soA + 32, Al + aoff + 8);
        cp16(sAL + soA + 48, Al + aoff + 12);
        long long boff = (long long)((kt << 5) + brow) * N + n0 + bcol;
        uint32_t soB = (uint32_t)(((buf * 32 + brow) * 136 + bcol) << 2);
        cp16(sB + soB,      B + boff);
        cp16(sB + soB + 16, B + boff + 4);
        cp16(sB + soB + 32, B + boff + 8);
        cp16(sB + soB + 48, B + boff + 12);
    };

    load_stage(0, 0);
    asm volatile("cp.async.commit_group;" ::: "memory");

    for (int kt = 0; kt < nk; kt++) {
        asm volatile("cp.async.wait_group 0;" ::: "memory");
        __syncthreads();
        if (kt + 1 < nk) {
            load_stage(kt + 1, (kt + 1) & 1);
            asm volatile("cp.async.commit_group;" ::: "memory");
        }
        const int buf = kt & 1;

        #pragma unroll
        for (int k8 = 0; k8 < 32; k8 += 8) {
            uint32_t ah[4][4], al[4][4];
            #pragma unroll
            for (int mt = 0; mt < 4; mt++) {
                uint32_t off = ((uint32_t)(((buf * 128 + aRow + mt * 16) * 36) + k8 + aColSel) << 2);
                LDMX4(ah[mt], sAH + off);
                LDMX4(al[mt], sAL + off);
            }
            uint32_t bh[4][2], bl[4][2];
            #pragma unroll
            for (int nt = 0; nt < 4; nt++) {
                #pragma unroll
                for (int j = 0; j < 2; j++) {
                    float f = Bsm[(buf * 32 + k8 + bkRow + j * 4) * 136 + bnCol + nt * 8];
                    float h = cvt_tf32(f);
                    bh[nt][j] = __float_as_uint(h);
                    bl[nt][j] = __float_as_uint(cvt_tf32(f - h));
                }
            }
            #pragma unroll
            for (int mt = 0; mt < 4; mt++)
                #pragma unroll
                for (int nt = 0; nt < 4; nt++) {
                    MMA_TF32(acc[mt][nt], ah[mt], bh[nt]);
                    MMA_TF32(acc[mt][nt], ah[mt], bl[nt]);
                    MMA_TF32(acc[mt][nt], al[mt], bh[nt]);
                }
        }
    }

    #pragma unroll
    for (int mt = 0; mt < 4; mt++) {
        #pragma unroll
        for (int half = 0; half < 2; half++) {
            int r = m0 + wm0 + mt * 16 + (lane >> 2) + half * 8;
            float b = bias[r];
            #pragma unroll
            for (int nt = 0; nt < 4; nt++) {
                int c = n0 + wn0 + nt * 8 + (lane & 3) * 2;
                long long off = (long long)r * N + c;
                *reinterpret_cast<float2*>(&C[off]) =
                    make_float2(acc[mt][nt][half * 2 + 0] + b,
                                acc[mt][nt][half * 2 + 1] + b);
            }
        }
    }
}

// ---------------- reduce 4 split-K partials + tf32 round --------------------
__global__ void reduce_kv(const float* __restrict__ p, float* __restrict__ out)
{
    const int per = CC * CC / 4;   // float4s per batch
    int i = blockIdx.x * 256 + threadIdx.x;
    if (i >= NB * per) return;
    int b = i / per, e = i % per;
    const float4* p4 = reinterpret_cast<const float4*>(p);
    float4 s0 = p4[((long long)b * 4 + 0) * per + e];
    float4 s1 = p4[((long long)b * 4 + 1) * per + e];
    float4 s2 = p4[((long long)b * 4 + 2) * per + e];
    float4 s3 = p4[((long long)b * 4 + 3) * per + e];
    float4 o;
    o.x = cvt_tf32(s0.x + s1.x + s2.x + s3.x);
    o.y = cvt_tf32(s0.y + s1.y + s2.y + s3.y);
    o.z = cvt_tf32(s0.z + s1.z + s2.z + s3.z);
    o.w = cvt_tf32(s0.w + s1.w + s2.w + s3.w);
    reinterpret_cast<float4*>(out)[i] = o;
}

// ---------------- elementwise tf32 round / split ----------------------------
__global__ void round_tf32_kernel(const float* __restrict__ in, float* __restrict__ out, int n4)
{
    int i = blockIdx.x * blockDim.x + threadIdx.x;
    if (i < n4) {
        float4 v = reinterpret_cast<const float4*>(in)[i];
        v.x = cvt_tf32(v.x); v.y = cvt_tf32(v.y);
        v.z = cvt_tf32(v.z); v.w = cvt_tf32(v.w);
        reinterpret_cast<float4*>(out)[i] = v;
    }
}

__global__ void split_tf32_kernel(const float* __restrict__ in,
                                  float* __restrict__ hi, float* __restrict__ lo, int n4)
{
    int i = blockIdx.x * blockDim.x + threadIdx.x;
    if (i < n4) {
        float4 v = reinterpret_cast<const float4*>(in)[i];
        float4 h, l;
        h.x = cvt_tf32(v.x); l.x = cvt_tf32(v.x - h.x);
        h.y = cvt_tf32(v.y); l.y = cvt_tf32(v.y - h.y);
        h.z = cvt_tf32(v.z); l.z = cvt_tf32(v.z - h.z);
        h.w = cvt_tf32(v.w); l.w = cvt_tf32(v.w - h.w);
        reinterpret_cast<float4*>(hi)[i] = h;
        reinterpret_cast<float4*>(lo)[i] = l;
    }
}

// ---------------- transposes -------------------------------------------------
__global__ void transpose_x(const float* __restrict__ x, float* __restrict__ out)
{
    __shared__ float tile[32][33];
    int b  = blockIdx.z;
    int s0 = blockIdx.x * 32, c0 = blockIdx.y * 32;
    const float* xb = x   + (long long)b * CC * SS;
    float*       ob = out + (long long)b * SS * CC;
    int tx = threadIdx.x, ty = threadIdx.y;
    #pragma unroll
    for (int i = 0; i < 32; i += 8)
        tile[ty + i][tx] = xb[(long long)(c0 + ty + i) * SS + s0 + tx];
    __syncthreads();
    #pragma unroll
    for (int i = 0; i < 32; i += 8)
        ob[(long long)(s0 + ty + i) * CC + c0 + tx] = tile[tx][ty + i];
}

__global__ void transpose_sc(const float* __restrict__ in, float* __restrict__ out)
{
    __shared__ float tile[32][33];
    int b  = blockIdx.z;
    int s0 = blockIdx.x * 32, c0 = blockIdx.y * 32;
    const float* ib = in  + (long long)b * SS * CC;
    float*       ob = out + (long long)b * CC * SS;
    int tx = threadIdx.x, ty = threadIdx.y;
    #pragma unroll
    for (int i = 0; i < 32; i += 8)
        tile[ty + i][tx] = ib[(long long)(s0 + ty + i) * CC + c0 + tx];
    __syncthreads();
    #pragma unroll
    for (int i = 0; i < 32; i += 8)
        ob[(long long)(c0 + ty + i) * SS + s0 + tx] = tile[tx][ty + i];
}

// ---------------- 3-phase column softmax ------------------------------------
__global__ void colsm_partial(const float* __restrict__ q,
                              float* __restrict__ pm, float* __restrict__ ps)
{
    int b = blockIdx.y, chunk = blockIdx.z;
    int col = blockIdx.x * 32 + threadIdx.x;
    int ry  = threadIdx.y;
    const float* base = q + (long long)b * SS * CC + col;
    int r0 = chunk * 256 + ry * 32;
    float m = -1e30f, s = 0.f;
    for (int i = r0; i < r0 + 32; ++i) {
        float v  = base[(long long)i * CC];
        float mn = fmaxf(m, v);
        s = s * __expf(m - mn) + __expf(v - mn);
        m = mn;
    }
    __shared__ float sm[8][32], ssh[8][32];
    sm[ry][threadIdx.x] = m; ssh[ry][threadIdx.x] = s;
    __syncthreads();
    if (ry == 0) {
        float M = sm[0][threadIdx.x], S = ssh[0][threadIdx.x];
        #pragma unroll
        for (int r2 = 1; r2 < 8; r2++) {
            float m2 = sm[r2][threadIdx.x], s2 = ssh[r2][threadIdx.x];
            float mn = fmaxf(M, m2);
            S = S * __expf(M - mn) + s2 * __expf(m2 - mn);
            M = mn;
        }
        int idx = (b * CC + col) * KCHUNK + chunk;
        pm[idx] = M; ps[idx] = S;
    }
}

__global__ void colsm_combine(const float* __restrict__ pm, const float* __restrict__ ps,
                              float* __restrict__ fm, float* __restrict__ fi)
{
    int i = blockIdx.x * blockDim.x + threadIdx.x;
    if (i >= NB * CC) return;
    float M = -1e30f, S = 0.f;
    #pragma unroll
    for (int c = 0; c < KCHUNK; c++) {
        float m2 = pm[i * KCHUNK + c], s2 = ps[i * KCHUNK + c];
        float mn = fmaxf(M, m2);
        S = S * __expf(M - mn) + s2 * __expf(m2 - mn);
        M = mn;
    }
    fm[i] = M; fi[i] = 1.f / S;
}

__global__ void colsm_norm(float* __restrict__ q, const float* __restrict__ fm,
                           const float* __restrict__ fi, const float* __restrict__ scale)
{
    int b = blockIdx.y, chunk = blockIdx.z;
    int col = blockIdx.x * 32 + threadIdx.x;
    int ry  = threadIdx.y;
    float* base = q + (long long)b * SS * CC + col;
    float M   = fm[b * CC + col];
    float inv = fi[b * CC + col];
    float isc = 1.f / log1pf(__expf(scale[col]));
    int r0 = chunk * 256 + ry * 32;
    for (int i = r0; i < r0 + 32; ++i) {
        float v = base[(long long)i * CC];
        base[(long long)i * CC] = (__expf(v - M) * inv + 1e-6f) * isc;
    }
}

// ---------------- q row renorm (tf32 out) + fused z --------------------------
__global__ void rownorm_pow3_z(float* __restrict__ buf, const float* __restrict__ ksum,
                               float* __restrict__ z)
{
    long long row = blockIdx.x;
    int b = (int)(row >> 12);
    float* p = buf + row * CC;
    const float* ks = ksum + b * CC;
    int t = threadIdx.x;
    float4 f4 = *reinterpret_cast<const float4*>(p + t * 4);
    float v[4] = { f4.x, f4.y, f4.z, f4.w };
    float s1 = 0.f;
    #pragma unroll
    for (int r = 0; r < 4; r++) s1 += v[r] * v[r];
    s1 = blockReduceSum(s1);
    float u3[4];
    float s3 = 0.f;
    #pragma unroll
    for (int r = 0; r < 4; r++) { u3[r] = v[r] * v[r] * v[r]; s3 += u3[r] * u3[r]; }
    s3 = blockReduceSum(s3);
    float f = sqrtf(s1) / sqrtf(s3);
    float o[4], dot = 0.f;
    #pragma unroll
    for (int r = 0; r < 4; r++) {
        o[r] = cvt_tf32(u3[r] * f);
        dot += o[r] * ks[t * 4 + r];
    }
    *reinterpret_cast<float4*>(p + t * 4) = make_float4(o[0], o[1], o[2], o[3]);
    dot = blockReduceSum(dot);
    if (t == 0) z[row] = 1.f / (dot + 1e-6f);
}

// ---------------- k: row softmax + transform + renorm + ksum (tf32) --------
__global__ void softmax_row_k(float* __restrict__ kbuf, const float* __restrict__ scale,
                              float* __restrict__ ksum)
{
    long long row = blockIdx.x;
    int b = (int)(row >> 12);
    float* p = kbuf + row * CC;
    int t = threadIdx.x;
    float4 f4 = *reinterpret_cast<const float4*>(p + t * 4);
    float v[4] = { f4.x, f4.y, f4.z, f4.w };
    float mx = fmaxf(fmaxf(v[0], v[1]), fmaxf(v[2], v[3]));
    mx = blockReduceMax(mx);
    float se = 0.f;
    #pragma unroll
    for (int r = 0; r < 4; r++) se += __expf(v[r] - mx);
    se = blockReduceSum(se);
    float inv = 1.f / se;
    float u[4];
    #pragma unroll
    for (int r = 0; r < 4; r++) {
        float isc = 1.f / log1pf(__expf(scale[t * 4 + r]));
        u[r] = (__expf(v[r] - mx) * inv + 1e-6f) * isc;
    }
    float s1 = 0.f;
    #pragma unroll
    for (int r = 0; r < 4; r++) s1 += u[r] * u[r];
    s1 = blockReduceSum(s1);
    float u3[4];
    float s3 = 0.f;
    #pragma unroll
    for (int r = 0; r < 4; r++) { u3[r] = u[r] * u[r] * u[r]; s3 += u3[r] * u3[r]; }
    s3 = blockReduceSum(s3);
    float f = sqrtf(s1) / sqrtf(s3);
    float o[4];
    #pragma unroll
    for (int r = 0; r < 4; r++) o[r] = cvt_tf32(u3[r] * f);
    *reinterpret_cast<float4*>(p + t * 4) = make_float4(o[0], o[1], o[2], o[3]);
    #pragma unroll
    for (int r = 0; r < 4; r++)
        atomicAdd(&ksum[b * CC + t * 4 + r], o[r]);
}

__global__ void zero_ksum(float* __restrict__ ksum)
{
    int i = blockIdx.x * blockDim.x + threadIdx.x;
    if (i < NB * CC) ksum[i] = 0.f;
}

// ---------------- LayerNorm over C=512 (tf32-rounded out) ------------------
__global__ void layernorm512(const float* __restrict__ in, float* __restrict__ out,
                             const float* __restrict__ g, const float* __restrict__ bta)
{
    long long row = blockIdx.x;
    const float* p = in + row * CC;
    int t = threadIdx.x;
    float4 f4 = *reinterpret_cast<const float4*>(p + t * 4);
    float v[4] = { f4.x, f4.y, f4.z, f4.w };
    float s = v[0] + v[1] + v[2] + v[3];
    s = blockReduceSum(s);
    float mean = s * (1.f / (float)CC);
    float s2 = 0.f;
    #pragma unroll
    for (int r = 0; r < 4; r++) { float d = v[r] - mean; s2 += d * d; }
    s2 = blockReduceSum(s2);
    float rstd = rsqrtf(s2 * (1.f / (float)CC) + 1e-5f);
    float o[4];
    #pragma unroll
    for (int r = 0; r < 4; r++) {
        int c = t * 4 + r;
        o[r] = cvt_tf32((v[r] - mean) * rstd * g[c] + bta[c]);
    }
    *reinterpret_cast<float4*>(out + row * CC + t * 4) = make_float4(o[0], o[1], o[2], o[3]);
}

// ---------------- depthwise 3x3 + residual + LN(HID) + GELU (tf32 out) -----
__global__ void dw_ln_gelu(const float* __restrict__ a, const float* __restrict__ w,
                           const float* __restrict__ wb, const float* __restrict__ g,
                           const float* __restrict__ beta, float* __restrict__ out)
{
    long long idx = blockIdx.x;
    int b = (int)(idx >> 12);
    int s = (int)(idx & 4095);
    int y = s >> 6, x = s & 63;
    int t = threadIdx.x;
    const float* ab = a + (long long)b * SS * HD;

    float val[8];
    float sum = 0.f;
    #pragma unroll
    for (int r = 0; r < 8; r++) {
        int h = r * 256 + t;
        float acc = wb[h];
        #pragma unroll
        for (int ky = 0; ky < 3; ky++) {
            int yy = y + ky - 1;
            if (yy < 0 || yy > 63) continue;
            #pragma unroll
            for (int kx = 0; kx < 3; kx++) {
                int xx = x + kx - 1;
                if (xx < 0 || xx > 63) continue;
                acc += w[h * 9 + ky * 3 + kx] * ab[((long long)(yy * 64 + xx)) * HD + h];
            }
        }
        acc += ab[(long long)s * HD + h];
        val[r] = acc;
        sum += acc;
    }
    sum = blockReduceSum(sum);
    float mean = sum * (1.f / (float)HD);
    float s2 = 0.f;
    #pragma unroll
    for (int r = 0; r < 8; r++) { float d = val[r] - mean; s2 += d * d; }
    s2 = blockReduceSum(s2);
    float rstd = rsqrtf(s2 * (1.f / (float)HD) + 1e-5f);
    #pragma unroll
    for (int r = 0; r < 8; r++) {
        int h = r * 256 + t;
        float yv = (val[r] - mean) * rstd * g[h] + beta[h];
        float ge = 0.5f * yv * (1.f + erff(yv * 0.70710678118654752f));
        out[idx * HD + h] = cvt_tf32(ge);
    }
}

// ---------------- launch ----------------------------------------------------
extern "C" void kernel_launch(void* const* d_in, const int* in_sizes, int n_in,
                              void* d_out, int out_size)
{
    const float* x      = (const float*)d_in[0];
    const float* Wq     = (const float*)d_in[1];
    const float* bq     = (const float*)d_in[2];
    const float* Wk     = (const float*)d_in[3];
    const float* bk     = (const float*)d_in[4];
    const float* Wv     = (const float*)d_in[5];
    const float* bv     = (const float*)d_in[6];
    const float* scale  = (const float*)d_in[7];
    const float* fc1_w  = (const float*)d_in[8];
    const float* fc1_b  = (const float*)d_in[9];
    const float* dw_w   = (const float*)d_in[10];
    const float* dw_b   = (const float*)d_in[11];
    const float* fc2_w  = (const float*)d_in[12];
    const float* fc2_b  = (const float*)d_in[13];
    const float* ln1_g  = (const float*)d_in[14];
    const float* ln1_b  = (const float*)d_in[15];
    const float* lnm_g  = (const float*)d_in[16];
    const float* lnm_b  = (const float*)d_in[17];
    float* out = (float*)d_out;

    void *pq, *pk, *pkt, *pv, *psc, *penh, *pt, *pa, *pax, *pkv, *pkvp;
    void *pwqh, *pwql, *pwkh, *pwkl, *pwv, *pw1, *pw2, *pksum, *pz;
    void *pcpm, *pcps, *pcfm, *pcfi;
    cudaGetSymbolAddress(&pq,   g_q);
    cudaGetSymbolAddress(&pk,   g_k);
    cudaGetSymbolAddress(&pkt,  g_kt);
    cudaGetSymbolAddress(&pv,   g_v);
    cudaGetSymbolAddress(&psc,  g_sc);
    cudaGetSymbolAddress(&penh, g_enh);
    cudaGetSymbolAddress(&pt,   g_t);
    cudaGetSymbolAddress(&pa,   g_a);
    cudaGetSymbolAddress(&pax,  g_ax);
    cudaGetSymbolAddress(&pkv,  g_kv);
    cudaGetSymbolAddress(&pkvp, g_kvp);
    cudaGetSymbolAddress(&pwqh, g_wqh);
    cudaGetSymbolAddress(&pwql, g_wql);
    cudaGetSymbolAddress(&pwkh, g_wkh);
    cudaGetSymbolAddress(&pwkl, g_wkl);
    cudaGetSymbolAddress(&pwv,  g_wv);
    cudaGetSymbolAddress(&pw1,  g_w1);
    cudaGetSymbolAddress(&pw2,  g_w2);
    cudaGetSymbolAddress(&pksum,g_ksum);
    cudaGetSymbolAddress(&pz,   g_z);
    cudaGetSymbolAddress(&pcpm, g_cpm);
    cudaGetSymbolAddress(&pcps, g_cps);
    cudaGetSymbolAddress(&pcfm, g_cfm);
    cudaGetSymbolAddress(&pcfi, g_cfi);

    cudaFuncSetAttribute(gemm_tc<0,true ,true ,false>, cudaFuncAttributeMaxDynamicSharedMemorySize, SMEM_GEMM_BYTES);
    cudaFuncSetAttribute(gemm_tc<1,false,false,true >, cudaFuncAttributeMaxDynamicSharedMemorySize, SMEM_GEMM_BYTES);
    cudaFuncSetAttribute(gemm_tc<2,false,false,false>, cudaFuncAttributeMaxDynamicSharedMemorySize, SMEM_GEMM_BYTES);
    cudaFuncSetAttribute(gemm_tc<3,false,false,false>, cudaFuncAttributeMaxDynamicSharedMemorySize, SMEM_GEMM_BYTES);
    cudaFuncSetAttribute(gemm_tc<4,false,false,false>, cudaFuncAttributeMaxDynamicSharedMemorySize, SMEM_GEMM_BYTES);
    cudaFuncSetAttribute(gemm_split2, cudaFuncAttributeMaxDynamicSharedMemorySize, SMEM_SPLIT2_BYTES);

    const long long BS  = (long long)CC * SS;
    const long long KVS = (long long)CC * CC;

    // 0. pre-round / pre-split weights (all L2-resident)
    round_tf32_kernel<<<(CC*HD/4 + 255)/256, 256>>>(fc1_w, (float*)pw1, CC*HD/4);
    round_tf32_kernel<<<(HD*CC/4 + 255)/256, 256>>>(fc2_w, (float*)pw2, HD*CC/4);
    round_tf32_kernel<<<(CC*CC/4 + 255)/256, 256>>>(Wv,    (float*)pwv, CC*CC/4);
    split_tf32_kernel<<<(CC*CC/4 + 255)/256, 256>>>(Wq, (float*)pwqh, (float*)pwql, CC*CC/4);
    split_tf32_kernel<<<(CC*CC/4 + 255)/256, 256>>>(Wk, (float*)pwkh, (float*)pwkl, CC*CC/4);

    // 1. shortcut = x^T per batch
    transpose_x<<<dim3(SS/32, CC/32, NB), dim3(32, 8)>>>(x, (float*)psc);

    // 2. qkv: q,k via split2 (W pre-split, x reg-split); v single-pass (B cvt)
    gemm_split2<<<dim3(SS/128, CC/128, NB), 256, SMEM_SPLIT2_BYTES>>>(
        (float*)pwqh, (float*)pwql, x, (float*)pq, CC, SS, CC, BS, BS, bq);
    gemm_split2<<<dim3(SS/128, CC/128, NB), 256, SMEM_SPLIT2_BYTES>>>(
        (float*)pwkh, (float*)pwkl, x, (float*)pk, CC, SS, CC, BS, BS, bk);
    gemm_tc<0,true ,true ,false><<<dim3(SS/128, CC/128, NB), 256, SMEM_GEMM_BYTES>>>(
        (float*)pwv, x, (float*)pv, CC, SS, CC, 0, BS, BS, bv, nullptr, 0, 0);

    // 3. k path (ksum needed by fused q kernel)
    zero_ksum<<<4, 1024>>>((float*)pksum);
    softmax_row_k<<<NB*SS, 128>>>((float*)pk, scale, (float*)pksum);
    transpose_sc<<<dim3(SS/32, CC/32, NB), dim3(32, 8)>>>((float*)pk, (float*)pkt);

    // 4. q path: 3-phase column softmax, then fused renorm^3 + z
    colsm_partial<<<dim3(CC/32, NB, KCHUNK), dim3(32, 8)>>>((float*)pq, (float*)pcpm, (float*)pcps);
    colsm_combine<<<(NB*CC + 255)/256, 256>>>((float*)pcpm, (float*)pcps, (float*)pcfm, (float*)pcfi);
    colsm_norm<<<dim3(CC/32, NB, KCHUNK), dim3(32, 8)>>>((float*)pq, (float*)pcfm, (float*)pcfi, scale);
    rownorm_pow3_z<<<NB*SS, 128>>>((float*)pq, (float*)pksum, (float*)pz);

    // 5. kv = kT @ v with 4-way split-K, then reduce + round
    gemm_tc<1,false,false,true ><<<dim3(CC/128, CC/128, NB*4), 256, SMEM_GEMM_BYTES>>>(
        (float*)pkt, (float*)pv, (float*)pkvp, CC, CC, SS, BS, BS, KVS,
        nullptr, nullptr, 0, 0);
    reduce_kv<<<(NB*CC*CC/4 + 255)/256, 256>>>((float*)pkvp, (float*)pkv);

    // 6. enhanced = shortcut + z * (q @ kv)
    gemm_tc<2,false,false,false><<<dim3(CC/128, SS/128, NB), 256, SMEM_GEMM_BYTES>>>(
        (float*)pq, (float*)pkv, (float*)penh, SS, CC, CC, BS, KVS, BS,
        (float*)pz, (float*)psc, SS, BS);

    // 7. t = LN(enhanced)
    layernorm512<<<NB*SS, 128>>>((float*)penh, (float*)pt, lnm_g, lnm_b);

    // 8. a = t @ w1 + fc1_b
    gemm_tc<3,false,false,false><<<dim3(HD/128, (NB*SS)/128, 1), 256, SMEM_GEMM_BYTES>>>(
        (float*)pt, (float*)pw1, (float*)pa, NB*SS, HD, CC, 0, 0, 0,
        fc1_b, nullptr, 0, 0);

    // 9. ax = gelu(LN(dwconv3x3(a) + dw_b + a))
    dw_ln_gelu<<<NB*SS, 256>>>((float*)pa, dw_w, dw_b, ln1_g, ln1_b, (float*)pax);

    // 10. out = enhanced + ax @ w2 + fc2_b
    gemm_tc<4,false,false,false><<<dim3(CC/128, (NB*SS)/128, 1), 256, SMEM_GEMM_BYTES>>>(
        (float*)pax, (float*)pw2, out, NB*SS, CC, HD, 0, 0, 0,
        fc2_b, (float*)penh, 0, 0);
}

// round 10
// speedup vs baseline: 1.0750x; 1.0750x over previous
#include <cuda_runtime.h>
#include <cuda_bf16.h>
#include <math.h>
#include <stdint.h>

// Problem dims
#define NB 8
#define CC 512
#define SS 4096     // N = H*W tokens
#define HD 2048     // HID = 4*C
#define HH 64

#define STAGES 4
#define KCHUNK 16   // column-softmax chunks

// ---------------- scratch (device globals; no allocation allowed) ----------
__device__ float g_q  [(long long)NB*CC*SS];
__device__ float g_k  [(long long)NB*CC*SS];
__device__ float g_kt [(long long)NB*CC*SS];
__device__ float g_v  [(long long)NB*CC*SS];
__device__ float g_sc [(long long)NB*SS*CC];
__device__ float g_enh[(long long)NB*SS*CC];
__device__ float g_t  [(long long)NB*SS*CC];
__device__ float g_a  [(long long)NB*SS*HD];
__device__ float g_ax [(long long)NB*SS*HD];
__device__ float g_kv [(long long)NB*CC*CC];
__device__ float g_kvp[(long long)4*NB*CC*CC];   // split-K partials
__device__ float g_wqh[CC*CC], g_wql[CC*CC];
__device__ float g_wkh[CC*CC], g_wkl[CC*CC];
__device__ float g_wv [CC*CC];
__device__ float g_w1 [(long long)CC*HD];
__device__ float g_w2 [(long long)HD*CC];
__device__ float g_ksum[NB*CC];
__device__ float g_z  [NB*SS];
__device__ float g_cpm[NB*CC*KCHUNK];
__device__ float g_cps[NB*CC*KCHUNK];
__device__ float g_cfm[NB*CC];
__device__ float g_cfi[NB*CC];

// ---------------- helpers ---------------------------------------------------
__device__ __forceinline__ float blockReduceSum(float val) {
    __shared__ float sh[32];
    int lane = threadIdx.x & 31, wid = threadIdx.x >> 5;
    #pragma unroll
    for (int o = 16; o > 0; o >>= 1) val += __shfl_xor_sync(0xffffffff, val, o);
    if (lane == 0) sh[wid] = val;
    __syncthreads();
    float tot = 0.f;
    if (wid == 0) {
        tot = (lane < (int)(blockDim.x >> 5)) ? sh[lane] : 0.f;
        #pragma unroll
        for (int o = 16; o > 0; o >>= 1) tot += __shfl_xor_sync(0xffffffff, tot, o);
        if (lane == 0) sh[0] = tot;
    }
    __syncthreads();
    tot = sh[0];
    __syncthreads();
    return tot;
}

__device__ __forceinline__ float blockReduceMax(float val) {
    __shared__ float sh[32];
    int lane = threadIdx.x & 31, wid = threadIdx.x >> 5;
    #pragma unroll
    for (int o = 16; o > 0; o >>= 1) val = fmaxf(val, __shfl_xor_sync(0xffffffff, val, o));
    if (lane == 0) sh[wid] = val;
    __syncthreads();
    float tot = -1e30f;
    if (wid == 0) {
        tot = (lane < (int)(blockDim.x >> 5)) ? sh[lane] : -1e30f;
        #pragma unroll
        for (int o = 16; o > 0; o >>= 1) tot = fmaxf(tot, __shfl_xor_sync(0xffffffff, tot, o));
        if (lane == 0) sh[0] = tot;
    }
    __syncthreads();
    tot = sh[0];
    __syncthreads();
    return tot;
}

__device__ __forceinline__ float cvt_tf32(float v) {
    uint32_t u;
    asm("cvt.rna.tf32.f32 %0, %1;" : "=r"(u) : "f"(v));
    return __uint_as_float(u);
}

__device__ __forceinline__ void cp16(uint32_t s, const void* g) {
    asm volatile("cp.async.cg.shared.global [%0], [%1], 16;" :: "r"(s), "l"(g));
}

#define MMA_TF32(d, a, b) \
    asm volatile("mma.sync.aligned.m16n8k8.row.col.f32.tf32.tf32.f32 " \
        "{%0,%1,%2,%3},{%4,%5,%6,%7},{%8,%9},{%0,%1,%2,%3};" \
        : "+f"(d[0]), "+f"(d[1]), "+f"(d[2]), "+f"(d[3]) \
        : "r"(a[0]), "r"(a[1]), "r"(a[2]), "r"(a[3]), "r"(b[0]), "r"(b[1]))

#define LDMX4(dst, addr) \
    asm volatile("ldmatrix.sync.aligned.m8n8.x4.shared.b16 {%0,%1,%2,%3}, [%4];" \
        : "=r"(dst[0]), "=r"(dst[1]), "=r"(dst[2]), "=r"(dst[3]) : "r"(addr) : "memory")

#define AS_FLOATS (STAGES * 128 * 20)
#define BS_FLOATS (STAGES * 16 * 136)
#define SMEM_GEMM_BYTES ((AS_FLOATS + BS_FLOATS) * 4)
// split2: 3 stages x (A hi + A lo + B)
#define SP_STAGES 3
#define SMEM_SPLIT2_BYTES ((SP_STAGES * (2*128*20 + 16*136)) * 4)

// ---------------- single-pass TF32 GEMM, BK=16, 4-stage cp.async -----------
// A must be pre-rounded tf32. B pre-rounded unless CVTB.
// MODE: 0 = +bias[row]; 1 = plain; 2 = acc*z[row]+shortcut; 3 = +bias[col];
//       4 = +bias[col]+res.  RND: tf32-round stores.  SPLITK: 4-way K split
//       (blockIdx.z = batch*4+slice, K param = lda, keff = 1024).
template<int MODE, bool CVTB, bool RND, bool SPLITK>
__global__ void __launch_bounds__(256, 2)
gemm_tc(const float* __restrict__ A, const float* __restrict__ B,
        float* __restrict__ C, int M, int N, int K,
        long long strA, long long strB, long long strC,
        const float* __restrict__ e0, const float* __restrict__ e1,
        long long strE0, long long strE1)
{
    extern __shared__ float smem[];
    float* Asm = smem;
    float* Bsm = smem + AS_FLOATS;

    int bz = blockIdx.z;
    int keff = K;
    if (SPLITK) {
        int slice = bz & 3;
        int batch = bz >> 2;
        A += (long long)batch * strA + slice * 1024;
        B += (long long)batch * strB + (long long)slice * 1024 * N;
        C += (long long)bz * strC;
        keff = 1024;
    } else {
        A += (long long)bz * strA;
        B += (long long)bz * strB;
        C += (long long)bz * strC;
    }
    const float* E0 = e0 ? e0 + (long long)bz * strE0 : nullptr;
    const float* E1 = e1 ? e1 + (long long)bz * strE1 : nullptr;

    const int t    = threadIdx.x;
    const int lane = t & 31, warp = t >> 5;
    const int m0   = blockIdx.y * 128, n0 = blockIdx.x * 128;
    const int wm0  = (warp & 1) * 64;
    const int wn0  = (warp >> 1) * 32;

    const int arow = t >> 1,  acol = (t & 1) * 8;
    const int brow = t >> 4,  bcol = (t & 15) * 8;

    const uint32_t sA = (uint32_t)__cvta_generic_to_shared(Asm);
    const uint32_t sB = (uint32_t)__cvta_generic_to_shared(Bsm);

    float acc[4][4][4];
    #pragma unroll
    for (int i = 0; i < 4; i++)
        #pragma unroll
        for (int j = 0; j < 4; j++)
            #pragma unroll
            for (int r = 0; r < 4; r++) acc[i][j][r] = 0.f;

    const int aRow    = wm0 + (lane & 15);
    const int aColSel = (lane >> 4) << 2;
    const int bkRow   = lane & 3;
    const int bnCol   = wn0 + (lane >> 2);

    const int nk = keff >> 4;

    auto load_stage = [&](int kt, int buf) {
        const float* ap = A + (long long)(m0 + arow) * K + (kt << 4) + acol;
        uint32_t sa = sA + (uint32_t)(((buf * 128 + arow) * 20 + acol) << 2);
        cp16(sa, ap);
        cp16(sa + 16, ap + 4);
        const float* bp = B + (long long)((kt << 4) + brow) * N + n0 + bcol;
        uint32_t sb = sB + (uint32_t)(((buf * 16 + brow) * 136 + bcol) << 2);
        cp16(sb, bp);
        cp16(sb + 16, bp + 4);
    };

    #pragma unroll
    for (int s = 0; s < STAGES - 1; s++) {
        if (s < nk) load_stage(s, s);
        asm volatile("cp.async.commit_group;" ::: "memory");
    }

    for (int kt = 0; kt < nk; kt++) {
        asm volatile("cp.async.wait_group %0;" :: "n"(STAGES - 2) : "memory");
        __syncthreads();
        {
            int pf = kt + STAGES - 1;
            if (pf < nk) load_stage(pf, pf & (STAGES - 1));
            asm volatile("cp.async.commit_group;" ::: "memory");
        }
        const int buf = kt & (STAGES - 1);

        #pragma unroll
        for (int k8 = 0; k8 < 16; k8 += 8) {
            uint32_t ah[4][4];
            #pragma unroll
            for (int mt = 0; mt < 4; mt++) {
                uint32_t addr = sA +
                    ((uint32_t)(((buf * 128 + aRow + mt * 16) * 20) + k8 + aColSel) << 2);
                LDMX4(ah[mt], addr);
            }
            uint32_t bh[4][2];
            #pragma unroll
            for (int nt = 0; nt < 4; nt++) {
                #pragma unroll
                for (int j = 0; j < 2; j++) {
                    float f = Bsm[(buf * 16 + k8 + bkRow + j * 4) * 136 + bnCol + nt * 8];
                    bh[nt][j] = __float_as_uint(CVTB ? cvt_tf32(f) : f);
                }
            }
            #pragma unroll
            for (int mt = 0; mt < 4; mt++)
                #pragma unroll
                for (int nt = 0; nt < 4; nt++)
                    MMA_TF32(acc[mt][nt], ah[mt], bh[nt]);
        }
    }

    #pragma unroll
    for (int mt = 0; mt < 4; mt++) {
        #pragma unroll
        for (int half = 0; half < 2; half++) {
            int r = m0 + wm0 + mt * 16 + (lane >> 2) + half * 8;
            #pragma unroll
            for (int nt = 0; nt < 4; nt++) {
                int c = n0 + wn0 + nt * 8 + (lane & 3) * 2;
                float v0 = acc[mt][nt][half * 2 + 0];
                float v1 = acc[mt][nt][half * 2 + 1];
                long long off = (long long)r * N + c;
                if (MODE == 0) { float b = E0[r]; v0 += b; v1 += b; }
                if (MODE == 2) {
                    float zz = E0[r];
                    float2 s = *reinterpret_cast<const float2*>(&E1[off]);
                    v0 = v0 * zz + s.x; v1 = v1 * zz + s.y;
                }
                if (MODE == 3) { v0 += E0[c]; v1 += E0[c + 1]; }
                if (MODE == 4) {
                    float2 s = *reinterpret_cast<const float2*>(&E1[off]);
                    v0 += E0[c] + s.x; v1 += E0[c + 1] + s.y;
                }
                if (RND) { v0 = cvt_tf32(v0); v1 = cvt_tf32(v1); }
                *reinterpret_cast<float2*>(&C[off]) = make_float2(v0, v1);
            }
        }
    }
}

// ---------------- split (3xTF32) GEMM: A pre-split planes, B reg-split ------
// C = Ah@Bh + Ah@Bl + Al@Bh + bias[row].  BK=16, 3-stage cp.async.
__global__ void __launch_bounds__(256, 2)
gemm_split2(const float* __restrict__ Ah, const float* __restrict__ Al,
            const float* __restrict__ B, float* __restrict__ C,
            int M, int N, int K, long long strB, long long strC,
            const float* __restrict__ bias)
{
    extern __shared__ float smem[];
    float* AsH = smem;                                  // [3][128][20]
    float* AsL = AsH + SP_STAGES * 128 * 20;
    float* Bsm = AsL + SP_STAGES * 128 * 20;            // [3][16][136]

    const int bz = blockIdx.z;
    B += (long long)bz * strB;
    C += (long long)bz * strC;

    const int t    = threadIdx.x;
    const int lane = t & 31, warp = t >> 5;
    const int m0   = blockIdx.y * 128, n0 = blockIdx.x * 128;
    const int wm0  = (warp & 1) * 64;
    const int wn0  = (warp >> 1) * 32;

    const int arow = t >> 1,  acol = (t & 1) * 8;
    const int brow = t >> 4,  bcol = (t & 15) * 8;

    const uint32_t sAH = (uint32_t)__cvta_generic_to_shared(AsH);
    const uint32_t sAL = (uint32_t)__cvta_generic_to_shared(AsL);
    const uint32_t sB  = (uint32_t)__cvta_generic_to_shared(Bsm);

    float acc[4][4][4];
    #pragma unroll
    for (int i = 0; i < 4; i++)
        #pragma unroll
        for (int j = 0; j < 4; j++)
            #pragma unroll
            for (int r = 0; r < 4; r++) acc[i][j][r] = 0.f;

    const int aRow    = wm0 + (lane & 15);
    const int aColSel = (lane >> 4) << 2;
    const int bkRow   = lane & 3;
    const int bnCol   = wn0 + (lane >> 2);

    const int nk = K >> 4;

    auto load_stage = [&](int kt, int buf) {
        long long aoff = (long long)(m0 + arow) * K + (kt << 4) + acol;
        uint32_t soA = (uint32_t)(((buf * 128 + arow) * 20 + acol) << 2);
        cp16(sAH + soA,      Ah + aoff);
        cp16(sAH + soA + 16, Ah + aoff + 4);
        cp16(sAL + soA,      Al + aoff);
        cp16(sAL + soA + 16, Al + aoff + 4);
        long long boff = (long long)((kt << 4) + brow) * N + n0 + bcol;
        uint32_t soB = (uint32_t)(((buf * 16 + brow) * 136 + bcol) << 2);
        cp16(sB + soB,      B + boff);
        cp16(sB + soB + 16, B + boff + 4);
    };

    #pragma unroll
    for (int s = 0; s < SP_STAGES - 1; s++) {
        if (s < nk) load_stage(s, s);
        asm volatile("cp.async.commit_group;" ::: "memory");
    }

    for (int kt = 0; kt < nk; kt++) {
        asm volatile("cp.async.wait_group 1;" ::: "memory");
        __syncthreads();
        {
            int pf = kt + SP_STAGES - 1;
            if (pf < nk) load_stage(pf, pf % SP_STAGES);
            asm volatile("cp.async.commit_group;" ::: "memory");
        }
        const int buf = kt % SP_STAGES;

        #pragma unroll
        for (int k8 = 0; k8 < 16; k8 += 8) {
            uint32_t ah[4][4], al[4][4];
            #pragma unroll
            for (int mt = 0; mt < 4; mt++) {
                uint32_t off = ((uint32_t)(((buf * 128 + aRow + mt * 16) * 20) + k8 + aColSel) << 2);
                LDMX4(ah[mt], sAH + off);
                LDMX4(al[mt], sAL + off);
            }
            uint32_t bh[4][2], bl[4][2];
            #pragma unroll
            for (int nt = 0; nt < 4; nt++) {
                #pragma unroll
                for (int j = 0; j < 2; j++) {
                    float f = Bsm[(buf * 16 + k8 + bkRow + j * 4) * 136 + bnCol + nt * 8];
                    float h = cvt_tf32(f);
                    bh[nt][j] = __float_as_uint(h);
                    bl[nt][j] = __float_as_uint(cvt_tf32(f - h));
                }
            }
            #pragma unroll
            for (int mt = 0; mt < 4; mt++)
                #pragma unroll
                for (int nt = 0; nt < 4; nt++) {
                    MMA_TF32(acc[mt][nt], ah[mt], bh[nt]);
                    MMA_TF32(acc[mt][nt], ah[mt], bl[nt]);
                    MMA_TF32(acc[mt][nt], al[mt], bh[nt]);
                }
        }
    }

    #pragma unroll
    for (int mt = 0; mt < 4; mt++) {
        #pragma unroll
        for (int half = 0; half < 2; half++) {
            int r = m0 + wm0 + mt * 16 + (lane >> 2) + half * 8;
            float b = bias[r];
            #pragma unroll
            for (int nt = 0; nt < 4; nt++) {
                int c = n0 + wn0 + nt * 8 + (lane & 3) * 2;
                long long off = (long long)r * N + c;
                *reinterpret_cast<float2*>(&C[off]) =
                    make_float2(acc[mt][nt][half * 2 + 0] + b,
                                acc[mt][nt][half * 2 + 1] + b);
            }
        }
    }
}

// ---------------- reduce 4 split-K partials + tf32 round --------------------
__global__ void reduce_kv(const float* __restrict__ p, float* __restrict__ out)
{
    const int per = CC * CC / 4;   // float4s per batch
    int i = blockIdx.x * 256 + threadIdx.x;
    if (i >= NB * per) return;
    int b = i / per, e = i % per;
    const float4* p4 = reinterpret_cast<const float4*>(p);
    float4 s0 = p4[((long long)b * 4 + 0) * per + e];
    float4 s1 = p4[((long long)b * 4 + 1) * per + e];
    float4 s2 = p4[((long long)b * 4 + 2) * per + e];
    float4 s3 = p4[((long long)b * 4 + 3) * per + e];
    float4 o;
    o.x = cvt_tf32(s0.x + s1.x + s2.x + s3.x);
    o.y = cvt_tf32(s0.y + s1.y + s2.y + s3.y);
    o.z = cvt_tf32(s0.z + s1.z + s2.z + s3.z);
    o.w = cvt_tf32(s0.w + s1.w + s2.w + s3.w);
    reinterpret_cast<float4*>(out)[i] = o;
}

// ---------------- elementwise tf32 round / split ----------------------------
__global__ void round_tf32_kernel(const float* __restrict__ in, float* __restrict__ out, int n4)
{
    int i = blockIdx.x * blockDim.x + threadIdx.x;
    if (i < n4) {
        float4 v = reinterpret_cast<const float4*>(in)[i];
        v.x = cvt_tf32(v.x); v.y = cvt_tf32(v.y);
        v.z = cvt_tf32(v.z); v.w = cvt_tf32(v.w);
        reinterpret_cast<float4*>(out)[i] = v;
    }
}

__global__ void split_tf32_kernel(const float* __restrict__ in,
                                  float* __restrict__ hi, float* __restrict__ lo, int n4)
{
    int i = blockIdx.x * blockDim.x + threadIdx.x;
    if (i < n4) {
        float4 v = reinterpret_cast<const float4*>(in)[i];
        float4 h, l;
        h.x = cvt_tf32(v.x); l.x = cvt_tf32(v.x - h.x);
        h.y = cvt_tf32(v.y); l.y = cvt_tf32(v.y - h.y);
        h.z = cvt_tf32(v.z); l.z = cvt_tf32(v.z - h.z);
        h.w = cvt_tf32(v.w); l.w = cvt_tf32(v.w - h.w);
        reinterpret_cast<float4*>(hi)[i] = h;
        reinterpret_cast<float4*>(lo)[i] = l;
    }
}

// ---------------- transposes -------------------------------------------------
__global__ void transpose_x(const float* __restrict__ x, float* __restrict__ out)
{
    __shared__ float tile[32][33];
    int b  = blockIdx.z;
    int s0 = blockIdx.x * 32, c0 = blockIdx.y * 32;
    const float* xb = x   + (long long)b * CC * SS;
    float*       ob = out + (long long)b * SS * CC;
    int tx = threadIdx.x, ty = threadIdx.y;
    #pragma unroll
    for (int i = 0; i < 32; i += 8)
        tile[ty + i][tx] = xb[(long long)(c0 + ty + i) * SS + s0 + tx];
    __syncthreads();
    #pragma unroll
    for (int i = 0; i < 32; i += 8)
        ob[(long long)(s0 + ty + i) * CC + c0 + tx] = tile[tx][ty + i];
}

__global__ void transpose_sc(const float* __restrict__ in, float* __restrict__ out)
{
    __shared__ float tile[32][33];
    int b  = blockIdx.z;
    int s0 = blockIdx.x * 32, c0 = blockIdx.y * 32;
    const float* ib = in  + (long long)b * SS * CC;
    float*       ob = out + (long long)b * CC * SS;
    int tx = threadIdx.x, ty = threadIdx.y;
    #pragma unroll
    for (int i = 0; i < 32; i += 8)
        tile[ty + i][tx] = ib[(long long)(s0 + ty + i) * CC + c0 + tx];
    __syncthreads();
    #pragma unroll
    for (int i = 0; i < 32; i += 8)
        ob[(long long)(c0 + ty + i) * SS + s0 + tx] = tile[tx][ty + i];
}

// ---------------- 3-phase column softmax ------------------------------------
__global__ void colsm_partial(const float* __restrict__ q,
                              float* __restrict__ pm, float* __restrict__ ps)
{
    int b = blockIdx.y, chunk = blockIdx.z;
    int col = blockIdx.x * 32 + threadIdx.x;
    int ry  = threadIdx.y;
    const float* base = q + (long long)b * SS * CC + col;
    int r0 = chunk * 256 + ry * 32;
    float m = -1e30f, s = 0.f;
    for (int i = r0; i < r0 + 32; ++i) {
        float v  = base[(long long)i * CC];
        float mn = fmaxf(m, v);
        s = s * __expf(m - mn) + __expf(v - mn);
        m = mn;
    }
    __shared__ float sm[8][32], ssh[8][32];
    sm[ry][threadIdx.x] = m; ssh[ry][threadIdx.x] = s;
    __syncthreads();
    if (ry == 0) {
        float M = sm[0][threadIdx.x], S = ssh[0][threadIdx.x];
        #pragma unroll
        for (int r2 = 1; r2 < 8; r2++) {
            float m2 = sm[r2][threadIdx.x], s2 = ssh[r2][threadIdx.x];
            float mn = fmaxf(M, m2);
            S = S * __expf(M - mn) + s2 * __expf(m2 - mn);
            M = mn;
        }
        int idx = (b * CC + col) * KCHUNK + chunk;
        pm[idx] = M; ps[idx] = S;
    }
}

__global__ void colsm_combine(const float* __restrict__ pm, const float* __restrict__ ps,
                              float* __restrict__ fm, float* __restrict__ fi)
{
    int i = blockIdx.x * blockDim.x + threadIdx.x;
    if (i >= NB * CC) return;
    float M = -1e30f, S = 0.f;
    #pragma unroll
    for (int c = 0; c < KCHUNK; c++) {
        float m2 = pm[i * KCHUNK + c], s2 = ps[i * KCHUNK + c];
        float mn = fmaxf(M, m2);
        S = S * __expf(M - mn) + s2 * __expf(m2 - mn);
        M = mn;
    }
    fm[i] = M; fi[i] = 1.f / S;
}

__global__ void colsm_norm(float* __restrict__ q, const float* __restrict__ fm,
                           const float* __restrict__ fi, const float* __restrict__ scale)
{
    int b = blockIdx.y, chunk = blockIdx.z;
    int col = blockIdx.x * 32 + threadIdx.x;
    int ry  = threadIdx.y;
    float* base = q + (long long)b * SS * CC + col;
    float M   = fm[b * CC + col];
    float inv = fi[b * CC + col];
    float isc = 1.f / log1pf(__expf(scale[col]));
    int r0 = chunk * 256 + ry * 32;
    for (int i = r0; i < r0 + 32; ++i) {
        float v = base[(long long)i * CC];
        base[(long long)i * CC] = (__expf(v - M) * inv + 1e-6f) * isc;
    }
}

// ---------------- q row renorm (tf32 out) + fused z --------------------------
__global__ void rownorm_pow3_z(float* __restrict__ buf, const float* __restrict__ ksum,
                               float* __restrict__ z)
{
    long long row = blockIdx.x;
    int b = (int)(row >> 12);
    float* p = buf + row * CC;
    const float* ks = ksum + b * CC;
    int t = threadIdx.x;
    float4 f4 = *reinterpret_cast<const float4*>(p + t * 4);
    float v[4] = { f4.x, f4.y, f4.z, f4.w };
    float s1 = 0.f;
    #pragma unroll
    for (int r = 0; r < 4; r++) s1 += v[r] * v[r];
    s1 = blockReduceSum(s1);
    float u3[4];
    float s3 = 0.f;
    #pragma unroll
    for (int r = 0; r < 4; r++) { u3[r] = v[r] * v[r] * v[r]; s3 += u3[r] * u3[r]; }
    s3 = blockReduceSum(s3);
    float f = sqrtf(s1) / sqrtf(s3);
    float o[4], dot = 0.f;
    #pragma unroll
    for (int r = 0; r < 4; r++) {
        o[r] = cvt_tf32(u3[r] * f);
        dot += o[r] * ks[t * 4 + r];
    }
    *reinterpret_cast<float4*>(p + t * 4) = make_float4(o[0], o[1], o[2], o[3]);
    dot = blockReduceSum(dot);
    if (t == 0) z[row] = 1.f / (dot + 1e-6f);
}

// ---------------- k: row softmax + transform + renorm + ksum (tf32) --------
__global__ void softmax_row_k(float* __restrict__ kbuf, const float* __restrict__ scale,
                              float* __restrict__ ksum)
{
    long long row = blockIdx.x;
    int b = (int)(row >> 12);
    float* p = kbuf + row * CC;
    int t = threadIdx.x;
    float4 f4 = *reinterpret_cast<const float4*>(p + t * 4);
    float v[4] = { f4.x, f4.y, f4.z, f4.w };
    float mx = fmaxf(fmaxf(v[0], v[1]), fmaxf(v[2], v[3]));
    mx = blockReduceMax(mx);
    float se = 0.f;
    #pragma unroll
    for (int r = 0; r < 4; r++) se += __expf(v[r] - mx);
    se = blockReduceSum(se);
    float inv = 1.f / se;
    float u[4];
    #pragma unroll
    for (int r = 0; r < 4; r++) {
        float isc = 1.f / log1pf(__expf(scale[t * 4 + r]));
        u[r] = (__expf(v[r] - mx) * inv + 1e-6f) * isc;
    }
    float s1 = 0.f;
    #pragma unroll
    for (int r = 0; r < 4; r++) s1 += u[r] * u[r];
    s1 = blockReduceSum(s1);
    float u3[4];
    float s3 = 0.f;
    #pragma unroll
    for (int r = 0; r < 4; r++) { u3[r] = u[r] * u[r] * u[r]; s3 += u3[r] * u3[r]; }
    s3 = blockReduceSum(s3);
    float f = sqrtf(s1) / sqrtf(s3);
    float o[4];
    #pragma unroll
    for (int r = 0; r < 4; r++) o[r] = cvt_tf32(u3[r] * f);
    *reinterpret_cast<float4*>(p + t * 4) = make_float4(o[0], o[1], o[2], o[3]);
    #pragma unroll
    for (int r = 0; r < 4; r++)
        atomicAdd(&ksum[b * CC + t * 4 + r], o[r]);
}

__global__ void zero_ksum(float* __restrict__ ksum)
{
    int i = blockIdx.x * blockDim.x + threadIdx.x;
    if (i < NB * CC) ksum[i] = 0.f;
}

// ---------------- LayerNorm over C=512 (tf32-rounded out) ------------------
__global__ void layernorm512(const float* __restrict__ in, float* __restrict__ out,
                             const float* __restrict__ g, const float* __restrict__ bta)
{
    long long row = blockIdx.x;
    const float* p = in + row * CC;
    int t = threadIdx.x;
    float4 f4 = *reinterpret_cast<const float4*>(p + t * 4);
    float v[4] = { f4.x, f4.y, f4.z, f4.w };
    float s = v[0] + v[1] + v[2] + v[3];
    s = blockReduceSum(s);
    float mean = s * (1.f / (float)CC);
    float s2 = 0.f;
    #pragma unroll
    for (int r = 0; r < 4; r++) { float d = v[r] - mean; s2 += d * d; }
    s2 = blockReduceSum(s2);
    float rstd = rsqrtf(s2 * (1.f / (float)CC) + 1e-5f);
    float o[4];
    #pragma unroll
    for (int r = 0; r < 4; r++) {
        int c = t * 4 + r;
        o[r] = cvt_tf32((v[r] - mean) * rstd * g[c] + bta[c]);
    }
    *reinterpret_cast<float4*>(out + row * CC + t * 4) = make_float4(o[0], o[1], o[2], o[3]);
}

// ---------------- depthwise 3x3 + residual + LN(HID) + GELU (tf32 out) -----
__global__ void dw_ln_gelu(const float* __restrict__ a, const float* __restrict__ w,
                           const float* __restrict__ wb, const float* __restrict__ g,
                           const float* __restrict__ beta, float* __restrict__ out)
{
    long long idx = blockIdx.x;
    int b = (int)(idx >> 12);
    int s = (int)(idx & 4095);
    int y = s >> 6, x = s & 63;
    int t = threadIdx.x;
    const float* ab = a + (long long)b * SS * HD;

    float val[8];
    float sum = 0.f;
    #pragma unroll
    for (int r = 0; r < 8; r++) {
        int h = r * 256 + t;
        float acc = wb[h];
        #pragma unroll
        for (int ky = 0; ky < 3; ky++) {
            int yy = y + ky - 1;
            if (yy < 0 || yy > 63) continue;
            #pragma unroll
            for (int kx = 0; kx < 3; kx++) {
                int xx = x + kx - 1;
                if (xx < 0 || xx > 63) continue;
                acc += w[h * 9 + ky * 3 + kx] * ab[((long long)(yy * 64 + xx)) * HD + h];
            }
        }
        acc += ab[(long long)s * HD + h];
        val[r] = acc;
        sum += acc;
    }
    sum = blockReduceSum(sum);
    float mean = sum * (1.f / (float)HD);
    float s2 = 0.f;
    #pragma unroll
    for (int r = 0; r < 8; r++) { float d = val[r] - mean; s2 += d * d; }
    s2 = blockReduceSum(s2);
    float rstd = rsqrtf(s2 * (1.f / (float)HD) + 1e-5f);
    #pragma unroll
    for (int r = 0; r < 8; r++) {
        int h = r * 256 + t;
        float yv = (val[r] - mean) * rstd * g[h] + beta[h];
        float ge = 0.5f * yv * (1.f + erff(yv * 0.70710678118654752f));
        out[idx * HD + h] = cvt_tf32(ge);
    }
}

// ---------------- launch ----------------------------------------------------
extern "C" void kernel_launch(void* const* d_in, const int* in_sizes, int n_in,
                              void* d_out, int out_size)
{
    const float* x      = (const float*)d_in[0];
    const float* Wq     = (const float*)d_in[1];
    const float* bq     = (const float*)d_in[2];
    const float* Wk     = (const float*)d_in[3];
    const float* bk     = (const float*)d_in[4];
    const float* Wv     = (const float*)d_in[5];
    const float* bv     = (const float*)d_in[6];
    const float* scale  = (const float*)d_in[7];
    const float* fc1_w  = (const float*)d_in[8];
    const float* fc1_b  = (const float*)d_in[9];
    const float* dw_w   = (const float*)d_in[10];
    const float* dw_b   = (const float*)d_in[11];
    const float* fc2_w  = (const float*)d_in[12];
    const float* fc2_b  = (const float*)d_in[13];
    const float* ln1_g  = (const float*)d_in[14];
    const float* ln1_b  = (const float*)d_in[15];
    const float* lnm_g  = (const float*)d_in[16];
    const float* lnm_b  = (const float*)d_in[17];
    float* out = (float*)d_out;

    void *pq, *pk, *pkt, *pv, *psc, *penh, *pt, *pa, *pax, *pkv, *pkvp;
    void *pwqh, *pwql, *pwkh, *pwkl, *pwv, *pw1, *pw2, *pksum, *pz;
    void *pcpm, *pcps, *pcfm, *pcfi;
    cudaGetSymbolAddress(&pq,   g_q);
    cudaGetSymbolAddress(&pk,   g_k);
    cudaGetSymbolAddress(&pkt,  g_kt);
    cudaGetSymbolAddress(&pv,   g_v);
    cudaGetSymbolAddress(&psc,  g_sc);
    cudaGetSymbolAddress(&penh, g_enh);
    cudaGetSymbolAddress(&pt,   g_t);
    cudaGetSymbolAddress(&pa,   g_a);
    cudaGetSymbolAddress(&pax,  g_ax);
    cudaGetSymbolAddress(&pkv,  g_kv);
    cudaGetSymbolAddress(&pkvp, g_kvp);
    cudaGetSymbolAddress(&pwqh, g_wqh);
    cudaGetSymbolAddress(&pwql, g_wql);
    cudaGetSymbolAddress(&pwkh, g_wkh);
    cudaGetSymbolAddress(&pwkl, g_wkl);
    cudaGetSymbolAddress(&pwv,  g_wv);
    cudaGetSymbolAddress(&pw1,  g_w1);
    cudaGetSymbolAddress(&pw2,  g_w2);
    cudaGetSymbolAddress(&pksum,g_ksum);
    cudaGetSymbolAddress(&pz,   g_z);
    cudaGetSymbolAddress(&pcpm, g_cpm);
    cudaGetSymbolAddress(&pcps, g_cps);
    cudaGetSymbolAddress(&pcfm, g_cfm);
    cudaGetSymbolAddress(&pcfi, g_cfi);

    cudaFuncSetAttribute(gemm_tc<0,true ,true ,false>, cudaFuncAttributeMaxDynamicSharedMemorySize, SMEM_GEMM_BYTES);
    cudaFuncSetAttribute(gemm_tc<1,false,false,true >, cudaFuncAttributeMaxDynamicSharedMemorySize, SMEM_GEMM_BYTES);
    cudaFuncSetAttribute(gemm_tc<2,false,false,false>, cudaFuncAttributeMaxDynamicSharedMemorySize, SMEM_GEMM_BYTES);
    cudaFuncSetAttribute(gemm_tc<3,false,false,false>, cudaFuncAttributeMaxDynamicSharedMemorySize, SMEM_GEMM_BYTES);
    cudaFuncSetAttribute(gemm_tc<4,false,false,false>, cudaFuncAttributeMaxDynamicSharedMemorySize, SMEM_GEMM_BYTES);
    cudaFuncSetAttribute(gemm_split2, cudaFuncAttributeMaxDynamicSharedMemorySize, SMEM_SPLIT2_BYTES);

    const long long BS  = (long long)CC * SS;
    const long long KVS = (long long)CC * CC;

    // 0. pre-round / pre-split weights (all L2-resident)
    round_tf32_kernel<<<(CC*HD/4 + 255)/256, 256>>>(fc1_w, (float*)pw1, CC*HD/4);
    round_tf32_kernel<<<(HD*CC/4 + 255)/256, 256>>>(fc2_w, (float*)pw2, HD*CC/4);
    round_tf32_kernel<<<(CC*CC/4 + 255)/256, 256>>>(Wv,    (float*)pwv, CC*CC/4);
    split_tf32_kernel<<<(CC*CC/4 + 255)/256, 256>>>(Wq, (float*)pwqh, (float*)pwql, CC*CC/4);
    split_tf32_kernel<<<(CC*CC/4 + 255)/256, 256>>>(Wk, (float*)pwkh, (float*)pwkl, CC*CC/4);

    // 1. shortcut = x^T per batch
    transpose_x<<<dim3(SS/32, CC/32, NB), dim3(32, 8)>>>(x, (float*)psc);

    // 2. qkv: q,k via split2 (W pre-split, x reg-split); v single-pass (B cvt)
    gemm_split2<<<dim3(SS/128, CC/128, NB), 256, SMEM_SPLIT2_BYTES>>>(
        (float*)pwqh, (float*)pwql, x, (float*)pq, CC, SS, CC, BS, BS, bq);
    gemm_split2<<<dim3(SS/128, CC/128, NB), 256, SMEM_SPLIT2_BYTES>>>(
        (float*)pwkh, (float*)pwkl, x, (float*)pk, CC, SS, CC, BS, BS, bk);
    gemm_tc<0,true ,true ,false><<<dim3(SS/128, CC/128, NB), 256, SMEM_GEMM_BYTES>>>(
        (float*)pwv, x, (float*)pv, CC, SS, CC, 0, BS, BS, bv, nullptr, 0, 0);

    // 3. k path (ksum needed by fused q kernel)
    zero_ksum<<<4, 1024>>>((float*)pksum);
    softmax_row_k<<<NB*SS, 128>>>((float*)pk, scale, (float*)pksum);
    transpose_sc<<<dim3(SS/32, CC/32, NB), dim3(32, 8)>>>((float*)pk, (float*)pkt);

    // 4. q path: 3-phase column softmax, then fused renorm^3 + z
    colsm_partial<<<dim3(CC/32, NB, KCHUNK), dim3(32, 8)>>>((float*)pq, (float*)pcpm, (float*)pcps);
    colsm_combine<<<(NB*CC + 255)/256, 256>>>((float*)pcpm, (float*)pcps, (float*)pcfm, (float*)pcfi);
    colsm_norm<<<dim3(CC/32, NB, KCHUNK), dim3(32, 8)>>>((float*)pq, (float*)pcfm, (float*)pcfi, scale);
    rownorm_pow3_z<<<NB*SS, 128>>>((float*)pq, (float*)pksum, (float*)pz);

    // 5. kv = kT @ v with 4-way split-K, then reduce + round
    gemm_tc<1,false,false,true ><<<dim3(CC/128, CC/128, NB*4), 256, SMEM_GEMM_BYTES>>>(
        (float*)pkt, (float*)pv, (float*)pkvp, CC, CC, SS, BS, BS, KVS,
        nullptr, nullptr, 0, 0);
    reduce_kv<<<(NB*CC*CC/4 + 255)/256, 256>>>((float*)pkvp, (float*)pkv);

    // 6. enhanced = shortcut + z * (q @ kv)
    gemm_tc<2,false,false,false><<<dim3(CC/128, SS/128, NB), 256, SMEM_GEMM_BYTES>>>(
        (float*)pq, (float*)pkv, (float*)penh, SS, CC, CC, BS, KVS, BS,
        (float*)pz, (float*)psc, SS, BS);

    // 7. t = LN(enhanced)
    layernorm512<<<NB*SS, 128>>>((float*)penh, (float*)pt, lnm_g, lnm_b);

    // 8. a = t @ w1 + fc1_b
    gemm_tc<3,false,false,false><<<dim3(HD/128, (NB*SS)/128, 1), 256, SMEM_GEMM_BYTES>>>(
        (float*)pt, (float*)pw1, (float*)pa, NB*SS, HD, CC, 0, 0, 0,
        fc1_b, nullptr, 0, 0);

    // 9. ax = gelu(LN(dwconv3x3(a) + dw_b + a))
    dw_ln_gelu<<<NB*SS, 256>>>((float*)pa, dw_w, dw_b, ln1_g, ln1_b, (float*)pax);

    // 10. out = enhanced + ax @ w2 + fc2_b
    gemm_tc<4,false,false,false><<<dim3(CC/128, (NB*SS)/128, 1), 256, SMEM_GEMM_BYTES>>>(
        (float*)pax, (float*)pw2, out, NB*SS, CC, HD, 0, 0, 0,
        fc2_b, (float*)penh, 0, 0);
}

// round 11
// speedup vs baseline: 1.1848x; 1.1022x over previous
#include <cuda_runtime.h>
#include <cuda_bf16.h>
#include <math.h>
#include <stdint.h>

// Problem dims
#define NB 8
#define CC 512
#define SS 4096     // N = H*W tokens
#define HD 2048     // HID = 4*C
#define HH 64

#define STAGES 4
#define KCHUNK 16   // column-softmax chunks

// ---------------- scratch (device globals; no allocation allowed) ----------
__device__ float g_q  [(long long)NB*CC*SS];
__device__ float g_k  [(long long)NB*CC*SS];
__device__ float g_kt [(long long)NB*CC*SS];
__device__ float g_v  [(long long)NB*CC*SS];
__device__ float g_sc [(long long)NB*SS*CC];
__device__ float g_enh[(long long)NB*SS*CC];
__device__ float g_t  [(long long)NB*SS*CC];
__device__ float g_a  [(long long)NB*SS*HD];
__device__ float g_ax [(long long)NB*SS*HD];
__device__ float g_kv [(long long)NB*CC*CC];
__device__ float g_kvp[(long long)4*NB*CC*CC];   // split-K partials
__device__ float g_wq [CC*CC];
__device__ float g_wk [CC*CC];
__device__ float g_wv [CC*CC];
__device__ float g_w1 [(long long)CC*HD];
__device__ float g_w2 [(long long)HD*CC];
__device__ float g_ksum[NB*CC];
__device__ float g_z  [NB*SS];
__device__ float g_cpm[NB*CC*KCHUNK];
__device__ float g_cps[NB*CC*KCHUNK];
__device__ float g_cfm[NB*CC];
__device__ float g_cfi[NB*CC];

// ---------------- helpers ---------------------------------------------------
__device__ __forceinline__ float blockReduceSum(float val) {
    __shared__ float sh[32];
    int lane = threadIdx.x & 31, wid = threadIdx.x >> 5;
    #pragma unroll
    for (int o = 16; o > 0; o >>= 1) val += __shfl_xor_sync(0xffffffff, val, o);
    if (lane == 0) sh[wid] = val;
    __syncthreads();
    float tot = 0.f;
    if (wid == 0) {
        tot = (lane < (int)(blockDim.x >> 5)) ? sh[lane] : 0.f;
        #pragma unroll
        for (int o = 16; o > 0; o >>= 1) tot += __shfl_xor_sync(0xffffffff, tot, o);
        if (lane == 0) sh[0] = tot;
    }
    __syncthreads();
    tot = sh[0];
    __syncthreads();
    return tot;
}

__device__ __forceinline__ float blockReduceMax(float val) {
    __shared__ float sh[32];
    int lane = threadIdx.x & 31, wid = threadIdx.x >> 5;
    #pragma unroll
    for (int o = 16; o > 0; o >>= 1) val = fmaxf(val, __shfl_xor_sync(0xffffffff, val, o));
    if (lane == 0) sh[wid] = val;
    __syncthreads();
    float tot = -1e30f;
    if (wid == 0) {
        tot = (lane < (int)(blockDim.x >> 5)) ? sh[lane] : -1e30f;
        #pragma unroll
        for (int o = 16; o > 0; o >>= 1) tot = fmaxf(tot, __shfl_xor_sync(0xffffffff, tot, o));
        if (lane == 0) sh[0] = tot;
    }
    __syncthreads();
    tot = sh[0];
    __syncthreads();
    return tot;
}

__device__ __forceinline__ float cvt_tf32(float v) {
    uint32_t u;
    asm("cvt.rna.tf32.f32 %0, %1;" : "=r"(u) : "f"(v));
    return __uint_as_float(u);
}

__device__ __forceinline__ void cp16(uint32_t s, const void* g) {
    asm volatile("cp.async.cg.shared.global [%0], [%1], 16;" :: "r"(s), "l"(g));
}

#define MMA_TF32(d, a, b) \
    asm volatile("mma.sync.aligned.m16n8k8.row.col.f32.tf32.tf32.f32 " \
        "{%0,%1,%2,%3},{%4,%5,%6,%7},{%8,%9},{%0,%1,%2,%3};" \
        : "+f"(d[0]), "+f"(d[1]), "+f"(d[2]), "+f"(d[3]) \
        : "r"(a[0]), "r"(a[1]), "r"(a[2]), "r"(a[3]), "r"(b[0]), "r"(b[1]))

#define LDMX4(dst, addr) \
    asm volatile("ldmatrix.sync.aligned.m8n8.x4.shared.b16 {%0,%1,%2,%3}, [%4];" \
        : "=r"(dst[0]), "=r"(dst[1]), "=r"(dst[2]), "=r"(dst[3]) : "r"(addr) : "memory")

#define AS_FLOATS (STAGES * 128 * 20)
#define BS_FLOATS (STAGES * 16 * 136)
#define SMEM_GEMM_BYTES ((AS_FLOATS + BS_FLOATS) * 4)

// ---------------- single-pass TF32 GEMM, BK=16, 4-stage cp.async -----------
// A must be pre-rounded tf32. B pre-rounded unless CVTB.
// MODE: 0 = +bias[row]; 1 = plain; 2 = acc*z[row]+shortcut; 3 = +bias[col];
//       4 = +bias[col]+res.  RND: tf32-round stores.  SPLITK: 4-way K split
//       (blockIdx.z = batch*4+slice, K param = lda, keff = 1024).
template<int MODE, bool CVTB, bool RND, bool SPLITK>
__global__ void __launch_bounds__(256, 2)
gemm_tc(const float* __restrict__ A, const float* __restrict__ B,
        float* __restrict__ C, int M, int N, int K,
        long long strA, long long strB, long long strC,
        const float* __restrict__ e0, const float* __restrict__ e1,
        long long strE0, long long strE1)
{
    extern __shared__ float smem[];
    float* Asm = smem;
    float* Bsm = smem + AS_FLOATS;

    int bz = blockIdx.z;
    int keff = K;
    if (SPLITK) {
        int slice = bz & 3;
        int batch = bz >> 2;
        A += (long long)batch * strA + slice * 1024;
        B += (long long)batch * strB + (long long)slice * 1024 * N;
        C += (long long)bz * strC;
        keff = 1024;
    } else {
        A += (long long)bz * strA;
        B += (long long)bz * strB;
        C += (long long)bz * strC;
    }
    const float* E0 = e0 ? e0 + (long long)bz * strE0 : nullptr;
    const float* E1 = e1 ? e1 + (long long)bz * strE1 : nullptr;

    const int t    = threadIdx.x;
    const int lane = t & 31, warp = t >> 5;
    const int m0   = blockIdx.y * 128, n0 = blockIdx.x * 128;
    const int wm0  = (warp & 1) * 64;
    const int wn0  = (warp >> 1) * 32;

    const int arow = t >> 1,  acol = (t & 1) * 8;
    const int brow = t >> 4,  bcol = (t & 15) * 8;

    const uint32_t sA = (uint32_t)__cvta_generic_to_shared(Asm);
    const uint32_t sB = (uint32_t)__cvta_generic_to_shared(Bsm);

    float acc[4][4][4];
    #pragma unroll
    for (int i = 0; i < 4; i++)
        #pragma unroll
        for (int j = 0; j < 4; j++)
            #pragma unroll
            for (int r = 0; r < 4; r++) acc[i][j][r] = 0.f;

    const int aRow    = wm0 + (lane & 15);
    const int aColSel = (lane >> 4) << 2;
    const int bkRow   = lane & 3;
    const int bnCol   = wn0 + (lane >> 2);

    const int nk = keff >> 4;

    auto load_stage = [&](int kt, int buf) {
        const float* ap = A + (long long)(m0 + arow) * K + (kt << 4) + acol;
        uint32_t sa = sA + (uint32_t)(((buf * 128 + arow) * 20 + acol) << 2);
        cp16(sa, ap);
        cp16(sa + 16, ap + 4);
        const float* bp = B + (long long)((kt << 4) + brow) * N + n0 + bcol;
        uint32_t sb = sB + (uint32_t)(((buf * 16 + brow) * 136 + bcol) << 2);
        cp16(sb, bp);
        cp16(sb + 16, bp + 4);
    };

    #pragma unroll
    for (int s = 0; s < STAGES - 1; s++) {
        if (s < nk) load_stage(s, s);
        asm volatile("cp.async.commit_group;" ::: "memory");
    }

    for (int kt = 0; kt < nk; kt++) {
        asm volatile("cp.async.wait_group %0;" :: "n"(STAGES - 2) : "memory");
        __syncthreads();
        {
            int pf = kt + STAGES - 1;
            if (pf < nk) load_stage(pf, pf & (STAGES - 1));
            asm volatile("cp.async.commit_group;" ::: "memory");
        }
        const int buf = kt & (STAGES - 1);

        #pragma unroll
        for (int k8 = 0; k8 < 16; k8 += 8) {
            uint32_t ah[4][4];
            #pragma unroll
            for (int mt = 0; mt < 4; mt++) {
                uint32_t addr = sA +
                    ((uint32_t)(((buf * 128 + aRow + mt * 16) * 20) + k8 + aColSel) << 2);
                LDMX4(ah[mt], addr);
            }
            uint32_t bh[4][2];
            #pragma unroll
            for (int nt = 0; nt < 4; nt++) {
                #pragma unroll
                for (int j = 0; j < 2; j++) {
                    float f = Bsm[(buf * 16 + k8 + bkRow + j * 4) * 136 + bnCol + nt * 8];
                    bh[nt][j] = __float_as_uint(CVTB ? cvt_tf32(f) : f);
                }
            }
            #pragma unroll
            for (int mt = 0; mt < 4; mt++)
                #pragma unroll
                for (int nt = 0; nt < 4; nt++)
                    MMA_TF32(acc[mt][nt], ah[mt], bh[nt]);
        }
    }

    #pragma unroll
    for (int mt = 0; mt < 4; mt++) {
        #pragma unroll
        for (int half = 0; half < 2; half++) {
            int r = m0 + wm0 + mt * 16 + (lane >> 2) + half * 8;
            #pragma unroll
            for (int nt = 0; nt < 4; nt++) {
                int c = n0 + wn0 + nt * 8 + (lane & 3) * 2;
                float v0 = acc[mt][nt][half * 2 + 0];
                float v1 = acc[mt][nt][half * 2 + 1];
                long long off = (long long)r * N + c;
                if (MODE == 0) { float b = E0[r]; v0 += b; v1 += b; }
                if (MODE == 2) {
                    float zz = E0[r];
                    float2 s = *reinterpret_cast<const float2*>(&E1[off]);
                    v0 = v0 * zz + s.x; v1 = v1 * zz + s.y;
                }
                if (MODE == 3) { v0 += E0[c]; v1 += E0[c + 1]; }
                if (MODE == 4) {
                    float2 s = *reinterpret_cast<const float2*>(&E1[off]);
                    v0 += E0[c] + s.x; v1 += E0[c + 1] + s.y;
                }
                if (RND) { v0 = cvt_tf32(v0); v1 = cvt_tf32(v1); }
                *reinterpret_cast<float2*>(&C[off]) = make_float2(v0, v1);
            }
        }
    }
}

// ---------------- reduce 4 split-K partials + tf32 round --------------------
__global__ void reduce_kv(const float* __restrict__ p, float* __restrict__ out)
{
    const int per = CC * CC / 4;   // float4s per batch
    int i = blockIdx.x * 256 + threadIdx.x;
    if (i >= NB * per) return;
    int b = i / per, e = i % per;
    const float4* p4 = reinterpret_cast<const float4*>(p);
    float4 s0 = p4[((long long)b * 4 + 0) * per + e];
    float4 s1 = p4[((long long)b * 4 + 1) * per + e];
    float4 s2 = p4[((long long)b * 4 + 2) * per + e];
    float4 s3 = p4[((long long)b * 4 + 3) * per + e];
    float4 o;
    o.x = cvt_tf32(s0.x + s1.x + s2.x + s3.x);
    o.y = cvt_tf32(s0.y + s1.y + s2.y + s3.y);
    o.z = cvt_tf32(s0.z + s1.z + s2.z + s3.z);
    o.w = cvt_tf32(s0.w + s1.w + s2.w + s3.w);
    reinterpret_cast<float4*>(out)[i] = o;
}

// ---------------- elementwise tf32 round ------------------------------------
__global__ void round_tf32_kernel(const float* __restrict__ in, float* __restrict__ out, int n4)
{
    int i = blockIdx.x * blockDim.x + threadIdx.x;
    if (i < n4) {
        float4 v = reinterpret_cast<const float4*>(in)[i];
        v.x = cvt_tf32(v.x); v.y = cvt_tf32(v.y);
        v.z = cvt_tf32(v.z); v.w = cvt_tf32(v.w);
        reinterpret_cast<float4*>(out)[i] = v;
    }
}

// ---------------- transposes -------------------------------------------------
__global__ void transpose_x(const float* __restrict__ x, float* __restrict__ out)
{
    __shared__ float tile[32][33];
    int b  = blockIdx.z;
    int s0 = blockIdx.x * 32, c0 = blockIdx.y * 32;
    const float* xb = x   + (long long)b * CC * SS;
    float*       ob = out + (long long)b * SS * CC;
    int tx = threadIdx.x, ty = threadIdx.y;
    #pragma unroll
    for (int i = 0; i < 32; i += 8)
        tile[ty + i][tx] = xb[(long long)(c0 + ty + i) * SS + s0 + tx];
    __syncthreads();
    #pragma unroll
    for (int i = 0; i < 32; i += 8)
        ob[(long long)(s0 + ty + i) * CC + c0 + tx] = tile[tx][ty + i];
}

__global__ void transpose_sc(const float* __restrict__ in, float* __restrict__ out)
{
    __shared__ float tile[32][33];
    int b  = blockIdx.z;
    int s0 = blockIdx.x * 32, c0 = blockIdx.y * 32;
    const float* ib = in  + (long long)b * SS * CC;
    float*       ob = out + (long long)b * CC * SS;
    int tx = threadIdx.x, ty = threadIdx.y;
    #pragma unroll
    for (int i = 0; i < 32; i += 8)
        tile[ty + i][tx] = ib[(long long)(s0 + ty + i) * CC + c0 + tx];
    __syncthreads();
    #pragma unroll
    for (int i = 0; i < 32; i += 8)
        ob[(long long)(c0 + ty + i) * SS + s0 + tx] = tile[tx][ty + i];
}

// ---------------- 3-phase column softmax ------------------------------------
__global__ void colsm_partial(const float* __restrict__ q,
                              float* __restrict__ pm, float* __restrict__ ps)
{
    int b = blockIdx.y, chunk = blockIdx.z;
    int col = blockIdx.x * 32 + threadIdx.x;
    int ry  = threadIdx.y;
    const float* base = q + (long long)b * SS * CC + col;
    int r0 = chunk * 256 + ry * 32;
    float m = -1e30f, s = 0.f;
    for (int i = r0; i < r0 + 32; ++i) {
        float v  = base[(long long)i * CC];
        float mn = fmaxf(m, v);
        s = s * __expf(m - mn) + __expf(v - mn);
        m = mn;
    }
    __shared__ float sm[8][32], ssh[8][32];
    sm[ry][threadIdx.x] = m; ssh[ry][threadIdx.x] = s;
    __syncthreads();
    if (ry == 0) {
        float M = sm[0][threadIdx.x], S = ssh[0][threadIdx.x];
        #pragma unroll
        for (int r2 = 1; r2 < 8; r2++) {
            float m2 = sm[r2][threadIdx.x], s2 = ssh[r2][threadIdx.x];
            float mn = fmaxf(M, m2);
            S = S * __expf(M - mn) + s2 * __expf(m2 - mn);
            M = mn;
        }
        int idx = (b * CC + col) * KCHUNK + chunk;
        pm[idx] = M; ps[idx] = S;
    }
}

__global__ void colsm_combine(const float* __restrict__ pm, const float* __restrict__ ps,
                              float* __restrict__ fm, float* __restrict__ fi)
{
    int i = blockIdx.x * blockDim.x + threadIdx.x;
    if (i >= NB * CC) return;
    float M = -1e30f, S = 0.f;
    #pragma unroll
    for (int c = 0; c < KCHUNK; c++) {
        float m2 = pm[i * KCHUNK + c], s2 = ps[i * KCHUNK + c];
        float mn = fmaxf(M, m2);
        S = S * __expf(M - mn) + s2 * __expf(m2 - mn);
        M = mn;
    }
    fm[i] = M; fi[i] = 1.f / S;
}

__global__ void colsm_norm(float* __restrict__ q, const float* __restrict__ fm,
                           const float* __restrict__ fi, const float* __restrict__ scale)
{
    int b = blockIdx.y, chunk = blockIdx.z;
    int col = blockIdx.x * 32 + threadIdx.x;
    int ry  = threadIdx.y;
    float* base = q + (long long)b * SS * CC + col;
    float M   = fm[b * CC + col];
    float inv = fi[b * CC + col];
    float isc = 1.f / log1pf(__expf(scale[col]));
    int r0 = chunk * 256 + ry * 32;
    for (int i = r0; i < r0 + 32; ++i) {
        float v = base[(long long)i * CC];
        base[(long long)i * CC] = (__expf(v - M) * inv + 1e-6f) * isc;
    }
}

// ---------------- q row renorm (tf32 out) + fused z --------------------------
__global__ void rownorm_pow3_z(float* __restrict__ buf, const float* __restrict__ ksum,
                               float* __restrict__ z)
{
    long long row = blockIdx.x;
    int b = (int)(row >> 12);
    float* p = buf + row * CC;
    const float* ks = ksum + b * CC;
    int t = threadIdx.x;
    float4 f4 = *reinterpret_cast<const float4*>(p + t * 4);
    float v[4] = { f4.x, f4.y, f4.z, f4.w };
    float s1 = 0.f;
    #pragma unroll
    for (int r = 0; r < 4; r++) s1 += v[r] * v[r];
    s1 = blockReduceSum(s1);
    float u3[4];
    float s3 = 0.f;
    #pragma unroll
    for (int r = 0; r < 4; r++) { u3[r] = v[r] * v[r] * v[r]; s3 += u3[r] * u3[r]; }
    s3 = blockReduceSum(s3);
    float f = sqrtf(s1) / sqrtf(s3);
    float o[4], dot = 0.f;
    #pragma unroll
    for (int r = 0; r < 4; r++) {
        o[r] = cvt_tf32(u3[r] * f);
        dot += o[r] * ks[t * 4 + r];
    }
    *reinterpret_cast<float4*>(p + t * 4) = make_float4(o[0], o[1], o[2], o[3]);
    dot = blockReduceSum(dot);
    if (t == 0) z[row] = 1.f / (dot + 1e-6f);
}

// ---------------- k: row softmax + transform + renorm + ksum (tf32) --------
__global__ void softmax_row_k(float* __restrict__ kbuf, const float* __restrict__ scale,
                              float* __restrict__ ksum)
{
    long long row = blockIdx.x;
    int b = (int)(row >> 12);
    float* p = kbuf + row * CC;
    int t = threadIdx.x;
    float4 f4 = *reinterpret_cast<const float4*>(p + t * 4);
    float v[4] = { f4.x, f4.y, f4.z, f4.w };
    float mx = fmaxf(fmaxf(v[0], v[1]), fmaxf(v[2], v[3]));
    mx = blockReduceMax(mx);
    float se = 0.f;
    #pragma unroll
    for (int r = 0; r < 4; r++) se += __expf(v[r] - mx);
    se = blockReduceSum(se);
    float inv = 1.f / se;
    float u[4];
    #pragma unroll
    for (int r = 0; r < 4; r++) {
        float isc = 1.f / log1pf(__expf(scale[t * 4 + r]));
        u[r] = (__expf(v[r] - mx) * inv + 1e-6f) * isc;
    }
    float s1 = 0.f;
    #pragma unroll
    for (int r = 0; r < 4; r++) s1 += u[r] * u[r];
    s1 = blockReduceSum(s1);
    float u3[4];
    float s3 = 0.f;
    #pragma unroll
    for (int r = 0; r < 4; r++) { u3[r] = u[r] * u[r] * u[r]; s3 += u3[r] * u3[r]; }
    s3 = blockReduceSum(s3);
    float f = sqrtf(s1) / sqrtf(s3);
    float o[4];
    #pragma unroll
    for (int r = 0; r < 4; r++) o[r] = cvt_tf32(u3[r] * f);
    *reinterpret_cast<float4*>(p + t * 4) = make_float4(o[0], o[1], o[2], o[3]);
    #pragma unroll
    for (int r = 0; r < 4; r++)
        atomicAdd(&ksum[b * CC + t * 4 + r], o[r]);
}

__global__ void zero_ksum(float* __restrict__ ksum)
{
    int i = blockIdx.x * blockDim.x + threadIdx.x;
    if (i < NB * CC) ksum[i] = 0.f;
}

// ---------------- LayerNorm over C=512 (tf32-rounded out) ------------------
__global__ void layernorm512(const float* __restrict__ in, float* __restrict__ out,
                             const float* __restrict__ g, const float* __restrict__ bta)
{
    long long row = blockIdx.x;
    const float* p = in + row * CC;
    int t = threadIdx.x;
    float4 f4 = *reinterpret_cast<const float4*>(p + t * 4);
    float v[4] = { f4.x, f4.y, f4.z, f4.w };
    float s = v[0] + v[1] + v[2] + v[3];
    s = blockReduceSum(s);
    float mean = s * (1.f / (float)CC);
    float s2 = 0.f;
    #pragma unroll
    for (int r = 0; r < 4; r++) { float d = v[r] - mean; s2 += d * d; }
    s2 = blockReduceSum(s2);
    float rstd = rsqrtf(s2 * (1.f / (float)CC) + 1e-5f);
    float o[4];
    #pragma unroll
    for (int r = 0; r < 4; r++) {
        int c = t * 4 + r;
        o[r] = cvt_tf32((v[r] - mean) * rstd * g[c] + bta[c]);
    }
    *reinterpret_cast<float4*>(out + row * CC + t * 4) = make_float4(o[0], o[1], o[2], o[3]);
}

// ---------------- depthwise 3x3 + residual + LN(HID) + GELU (tf32 out) -----
__global__ void dw_ln_gelu(const float* __restrict__ a, const float* __restrict__ w,
                           const float* __restrict__ wb, const float* __restrict__ g,
                           const float* __restrict__ beta, float* __restrict__ out)
{
    long long idx = blockIdx.x;
    int b = (int)(idx >> 12);
    int s = (int)(idx & 4095);
    int y = s >> 6, x = s & 63;
    int t = threadIdx.x;
    const float* ab = a + (long long)b * SS * HD;

    float val[8];
    float sum = 0.f;
    #pragma unroll
    for (int r = 0; r < 8; r++) {
        int h = r * 256 + t;
        float acc = wb[h];
        #pragma unroll
        for (int ky = 0; ky < 3; ky++) {
            int yy = y + ky - 1;
            if (yy < 0 || yy > 63) continue;
            #pragma unroll
            for (int kx = 0; kx < 3; kx++) {
                int xx = x + kx - 1;
                if (xx < 0 || xx > 63) continue;
                acc += w[h * 9 + ky * 3 + kx] * ab[((long long)(yy * 64 + xx)) * HD + h];
            }
        }
        acc += ab[(long long)s * HD + h];
        val[r] = acc;
        sum += acc;
    }
    sum = blockReduceSum(sum);
    float mean = sum * (1.f / (float)HD);
    float s2 = 0.f;
    #pragma unroll
    for (int r = 0; r < 8; r++) { float d = val[r] - mean; s2 += d * d; }
    s2 = blockReduceSum(s2);
    float rstd = rsqrtf(s2 * (1.f / (float)HD) + 1e-5f);
    #pragma unroll
    for (int r = 0; r < 8; r++) {
        int h = r * 256 + t;
        float yv = (val[r] - mean) * rstd * g[h] + beta[h];
        float ge = 0.5f * yv * (1.f + erff(yv * 0.70710678118654752f));
        out[idx * HD + h] = cvt_tf32(ge);
    }
}

// ---------------- launch ----------------------------------------------------
extern "C" void kernel_launch(void* const* d_in, const int* in_sizes, int n_in,
                              void* d_out, int out_size)
{
    const float* x      = (const float*)d_in[0];
    const float* Wq     = (const float*)d_in[1];
    const float* bq     = (const float*)d_in[2];
    const float* Wk     = (const float*)d_in[3];
    const float* bk     = (const float*)d_in[4];
    const float* Wv     = (const float*)d_in[5];
    const float* bv     = (const float*)d_in[6];
    const float* scale  = (const float*)d_in[7];
    const float* fc1_w  = (const float*)d_in[8];
    const float* fc1_b  = (const float*)d_in[9];
    const float* dw_w   = (const float*)d_in[10];
    const float* dw_b   = (const float*)d_in[11];
    const float* fc2_w  = (const float*)d_in[12];
    const float* fc2_b  = (const float*)d_in[13];
    const float* ln1_g  = (const float*)d_in[14];
    const float* ln1_b  = (const float*)d_in[15];
    const float* lnm_g  = (const float*)d_in[16];
    const float* lnm_b  = (const float*)d_in[17];
    float* out = (float*)d_out;

    void *pq, *pk, *pkt, *pv, *psc, *penh, *pt, *pa, *pax, *pkv, *pkvp;
    void *pwq, *pwk, *pwv, *pw1, *pw2, *pksum, *pz;
    void *pcpm, *pcps, *pcfm, *pcfi;
    cudaGetSymbolAddress(&pq,   g_q);
    cudaGetSymbolAddress(&pk,   g_k);
    cudaGetSymbolAddress(&pkt,  g_kt);
    cudaGetSymbolAddress(&pv,   g_v);
    cudaGetSymbolAddress(&psc,  g_sc);
    cudaGetSymbolAddress(&penh, g_enh);
    cudaGetSymbolAddress(&pt,   g_t);
    cudaGetSymbolAddress(&pa,   g_a);
    cudaGetSymbolAddress(&pax,  g_ax);
    cudaGetSymbolAddress(&pkv,  g_kv);
    cudaGetSymbolAddress(&pkvp, g_kvp);
    cudaGetSymbolAddress(&pwq,  g_wq);
    cudaGetSymbolAddress(&pwk,  g_wk);
    cudaGetSymbolAddress(&pwv,  g_wv);
    cudaGetSymbolAddress(&pw1,  g_w1);
    cudaGetSymbolAddress(&pw2,  g_w2);
    cudaGetSymbolAddress(&pksum,g_ksum);
    cudaGetSymbolAddress(&pz,   g_z);
    cudaGetSymbolAddress(&pcpm, g_cpm);
    cudaGetSymbolAddress(&pcps, g_cps);
    cudaGetSymbolAddress(&pcfm, g_cfm);
    cudaGetSymbolAddress(&pcfi, g_cfi);

    cudaFuncSetAttribute(gemm_tc<0,true ,true ,false>, cudaFuncAttributeMaxDynamicSharedMemorySize, SMEM_GEMM_BYTES);
    cudaFuncSetAttribute(gemm_tc<0,true ,false,false>, cudaFuncAttributeMaxDynamicSharedMemorySize, SMEM_GEMM_BYTES);
    cudaFuncSetAttribute(gemm_tc<1,false,false,true >, cudaFuncAttributeMaxDynamicSharedMemorySize, SMEM_GEMM_BYTES);
    cudaFuncSetAttribute(gemm_tc<2,false,false,false>, cudaFuncAttributeMaxDynamicSharedMemorySize, SMEM_GEMM_BYTES);
    cudaFuncSetAttribute(gemm_tc<3,false,false,false>, cudaFuncAttributeMaxDynamicSharedMemorySize, SMEM_GEMM_BYTES);
    cudaFuncSetAttribute(gemm_tc<4,false,false,false>, cudaFuncAttributeMaxDynamicSharedMemorySize, SMEM_GEMM_BYTES);

    const long long BS  = (long long)CC * SS;
    const long long KVS = (long long)CC * CC;

    // 0. pre-round weights to tf32 (all L2-resident)
    round_tf32_kernel<<<(CC*HD/4 + 255)/256, 256>>>(fc1_w, (float*)pw1, CC*HD/4);
    round_tf32_kernel<<<(HD*CC/4 + 255)/256, 256>>>(fc2_w, (float*)pw2, HD*CC/4);
    round_tf32_kernel<<<(CC*CC/4 + 255)/256, 256>>>(Wq, (float*)pwq, CC*CC/4);
    round_tf32_kernel<<<(CC*CC/4 + 255)/256, 256>>>(Wk, (float*)pwk, CC*CC/4);
    round_tf32_kernel<<<(CC*CC/4 + 255)/256, 256>>>(Wv, (float*)pwv, CC*CC/4);

    // 1. shortcut = x^T per batch
    transpose_x<<<dim3(SS/32, CC/32, NB), dim3(32, 8)>>>(x, (float*)psc);

    // 2. qkv: all single-pass tf32 (W pre-rounded; x converted in regs)
    gemm_tc<0,true ,false,false><<<dim3(SS/128, CC/128, NB), 256, SMEM_GEMM_BYTES>>>(
        (float*)pwq, x, (float*)pq, CC, SS, CC, 0, BS, BS, bq, nullptr, 0, 0);
    gemm_tc<0,true ,false,false><<<dim3(SS/128, CC/128, NB), 256, SMEM_GEMM_BYTES>>>(
        (float*)pwk, x, (float*)pk, CC, SS, CC, 0, BS, BS, bk, nullptr, 0, 0);
    gemm_tc<0,true ,true ,false><<<dim3(SS/128, CC/128, NB), 256, SMEM_GEMM_BYTES>>>(
        (float*)pwv, x, (float*)pv, CC, SS, CC, 0, BS, BS, bv, nullptr, 0, 0);

    // 3. k path (ksum needed by fused q kernel)
    zero_ksum<<<4, 1024>>>((float*)pksum);
    softmax_row_k<<<NB*SS, 128>>>((float*)pk, scale, (float*)pksum);
    transpose_sc<<<dim3(SS/32, CC/32, NB), dim3(32, 8)>>>((float*)pk, (float*)pkt);

    // 4. q path: 3-phase column softmax, then fused renorm^3 + z
    colsm_partial<<<dim3(CC/32, NB, KCHUNK), dim3(32, 8)>>>((float*)pq, (float*)pcpm, (float*)pcps);
    colsm_combine<<<(NB*CC + 255)/256, 256>>>((float*)pcpm, (float*)pcps, (float*)pcfm, (float*)pcfi);
    colsm_norm<<<dim3(CC/32, NB, KCHUNK), dim3(32, 8)>>>((float*)pq, (float*)pcfm, (float*)pcfi, scale);
    rownorm_pow3_z<<<NB*SS, 128>>>((float*)pq, (float*)pksum, (float*)pz);

    // 5. kv = kT @ v with 4-way split-K, then reduce + round
    gemm_tc<1,false,false,true ><<<dim3(CC/128, CC/128, NB*4), 256, SMEM_GEMM_BYTES>>>(
        (float*)pkt, (float*)pv, (float*)pkvp, CC, CC, SS, BS, BS, KVS,
        nullptr, nullptr, 0, 0);
    reduce_kv<<<(NB*CC*CC/4 + 255)/256, 256>>>((float*)pkvp, (float*)pkv);

    // 6. enhanced = shortcut + z * (q @ kv)
    gemm_tc<2,false,false,false><<<dim3(CC/128, SS/128, NB), 256, SMEM_GEMM_BYTES>>>(
        (float*)pq, (float*)pkv, (float*)penh, SS, CC, CC, BS, KVS, BS,
        (float*)pz, (float*)psc, SS, BS);

    // 7. t = LN(enhanced)
    layernorm512<<<NB*SS, 128>>>((float*)penh, (float*)pt, lnm_g, lnm_b);

    // 8. a = t @ w1 + fc1_b
    gemm_tc<3,false,false,false><<<dim3(HD/128, (NB*SS)/128, 1), 256, SMEM_GEMM_BYTES>>>(
        (float*)pt, (float*)pw1, (float*)pa, NB*SS, HD, CC, 0, 0, 0,
        fc1_b, nullptr, 0, 0);

    // 9. ax = gelu(LN(dwconv3x3(a) + dw_b + a))
    dw_ln_gelu<<<NB*SS, 256>>>((float*)pa, dw_w, dw_b, ln1_g, ln1_b, (float*)pax);

    // 10. out = enhanced + ax @ w2 + fc2_b
    gemm_tc<4,false,false,false><<<dim3(CC/128, (NB*SS)/128, 1), 256, SMEM_GEMM_BYTES>>>(
        (float*)pax, (float*)pw2, out, NB*SS, CC, HD, 0, 0, 0,
        fc2_b, (float*)penh, 0, 0);
}